// round 8
// baseline (speedup 1.0000x reference)
#include <cuda_runtime.h>
#include <cuda_bf16.h>
#include <cuda_fp16.h>
#include <math.h>
#include <stdint.h>

#define G_CNT 1024
#define A_CNT 20
#define N_CNT (G_CNT * A_CNT)          // 20480
#define E_CNT (G_CNT * A_CNT * A_CNT)  // 409600
#define H_DIM 128
#define NLAYER 4

typedef unsigned long long u64;
typedef unsigned int u32;
typedef unsigned short u16;

// ---------------- scratch (device globals) ----------------
__device__ float g_h[N_CNT * H_DIM];
__device__ float g_hs[N_CNT * H_DIM];
__device__ float g_hd[N_CNT * H_DIM];
__device__ float g_agg[N_CNT * H_DIM];
__device__ float g_latip[G_CNT * 9];
__device__ float g_latterm[G_CNT * H_DIM];
__device__ float g_embT[100 * H_DIM];            // emb_table @ w_latent[:128]
__device__ u16 g_disH[(size_t)E_CNT * 64];       // dis fp16 [edge][64]
// fp16 weights, consumer-ready K-major [n][k]
__device__ u16 g_w1d[NLAYER * 128 * 64];
__device__ u16 g_w1n[NLAYER * 256 * 128];
__device__ u16 g_w2[NLAYER * 128 * 128];
__device__ u16 g_nw1[NLAYER * 128 * 256];
__device__ u16 g_nw2[NLAYER * 128 * 128];

__device__ __forceinline__ float siluf(float x) {
    return __fdividef(x, 1.0f + __expf(-x));
}
// fast silu: 1 MUFU (tanh) + 2 flops. silu(x) = m + m*tanh(m), m = x/2
__device__ __forceinline__ float silu_t(float x) {
    float m = 0.5f * x, t;
    asm("tanh.approx.f32 %0, %1;" : "=f"(t) : "f"(m));
    return fmaf(m, t, m);
}
__device__ __forceinline__ u16 h_rn(float x) {
    return __half_as_ushort(__float2half_rn(x));
}
__device__ __forceinline__ u32 pack_h2(float a, float b) {
    __half2 hh = __floats2half2_rn(a, b);
    return *(u32*)&hh;
}

__device__ __forceinline__ void mma_f16(float c[4], const u32 a[4], u32 b0, u32 b1) {
    asm volatile(
        "mma.sync.aligned.m16n8k16.row.col.f32.f16.f16.f32 "
        "{%0,%1,%2,%3}, {%4,%5,%6,%7}, {%8,%9}, {%0,%1,%2,%3};"
        : "+f"(c[0]), "+f"(c[1]), "+f"(c[2]), "+f"(c[3])
        : "r"(a[0]), "r"(a[1]), "r"(a[2]), "r"(a[3]), "r"(b0), "r"(b1));
}

// ---------------- weight prep: fp32 -> fp16 K-major, once ----------------
__global__ __launch_bounds__(256) void k_prep(
    const float* __restrict__ ew1, const float* __restrict__ ew2,
    const float* __restrict__ nw1, const float* __restrict__ nw2)
{
    int i = blockIdx.x * 256 + threadIdx.x;
    if (i >= NLAYER * 106496) return;
    int L = i / 106496, j = i % 106496;
    const float* e1 = ew1 + L * 325 * 128;
    const float* e2 = ew2 + L * 128 * 128;
    const float* n1 = nw1 + L * 256 * 128;
    const float* n2 = nw2 + L * 128 * 128;
    if (j < 8192) {                       // w1d [n=128][k=64], pad k>=60
        int n = j >> 6, k = j & 63;
        float v = (k < 60) ? e1[(265 + k) * 128 + n] : 0.f;
        g_w1d[L * 8192 + j] = h_rn(v);
    } else if (j < 40960) {               // w1n [n=256][k=128]
        int jj = j - 8192;
        int n = jj >> 7, k = jj & 127;
        float v = (n < 128) ? e1[k * 128 + n] : e1[(128 + k) * 128 + (n - 128)];
        g_w1n[L * 32768 + jj] = h_rn(v);
    } else if (j < 57344) {               // w2 [n=128][k=128]
        int jj = j - 40960;
        int n = jj >> 7, k = jj & 127;
        g_w2[L * 16384 + jj] = h_rn(e2[k * 128 + n]);
    } else if (j < 90112) {               // nw1 [n=128][k=256]
        int jj = j - 57344;
        int n = jj >> 8, k = jj & 255;
        g_nw1[L * 32768 + jj] = h_rn(n1[k * 128 + n]);
    } else {                              // nw2 [n=128][k=128]
        int jj = j - 90112;
        int n = jj >> 7, k = jj & 127;
        g_nw2[L * 16384 + jj] = h_rn(n2[k * 128 + n]);
    }
}

// ---------------- embT[a] = emb_table[a] @ w_latent[:128] ----------------
__global__ __launch_bounds__(128) void k_prep_emb(
    const float* __restrict__ emb_table, const float* __restrict__ w_latent)
{
    int a = blockIdx.x, c = threadIdx.x;
    float s = 0.f;
#pragma unroll 4
    for (int k = 0; k < 128; ++k)
        s = fmaf(emb_table[a * 128 + k], w_latent[k * 128 + c], s);
    g_embT[a * 128 + c] = s;
}

// ---------------- lat_ip = L @ L^T ----------------
__global__ void k_latip(const float* __restrict__ lattices) {
    int g = blockIdx.x, tid = threadIdx.x;
    if (tid < 9) {
        int i = tid / 3, k = tid % 3;
        float s = 0.f;
#pragma unroll
        for (int j = 0; j < 3; ++j)
            s += lattices[g * 9 + i * 3 + j] * lattices[g * 9 + k * 3 + j];
        g_latip[g * 9 + tid] = s;
    }
}

// ---------------- dis embedding -> fp16, [e][64] ----------------
// smem row stride 33 u32 (66 u16): lane i row base lands on bank i -> no conflicts
__global__ __launch_bounds__(128) void k_dis(const float* __restrict__ fc) {
    __shared__ u32 hiS[128 * 33];
    int tid = threadIdx.x;
    size_t e0 = (size_t)blockIdx.x * 128;
    int e = (int)e0 + tid;
    int g = e / 400, r = e % 400;
    int src = g * 20 + r / 20;
    int dst = g * 20 + r % 20;
    u16* hrow = (u16*)(hiS + tid * 33);
#pragma unroll
    for (int c = 0; c < 3; ++c) {
        float d = fc[dst * 3 + c] - fc[src * 3 + c];
        d -= floorf(d);
        float s1, c1;
        sincospif(2.0f * d, &s1, &c1);
        float s = 0.f, co = 1.f;
        hrow[c * 10] = 0;
        hrow[30 + c * 10] = h_rn(1.f);
#pragma unroll
        for (int f = 1; f < 10; ++f) {
            float ns = s * c1 + co * s1;
            float nc = co * c1 - s * s1;
            s = ns; co = nc;
            hrow[c * 10 + f] = h_rn(s);
            hrow[30 + c * 10 + f] = h_rn(co);
        }
    }
#pragma unroll
    for (int k = 60; k < 64; ++k) hrow[k] = 0;
    __syncthreads();
    u32* gh = (u32*)g_disH + e0 * 32;
    for (int i = tid; i < 4096; i += 128)
        gh[i] = hiS[(i >> 5) * 33 + (i & 31)];
}

// ---------------- node embedding: gather(embT) + per-graph t-latent ------
__global__ __launch_bounds__(128) void k_embed(
    const int* __restrict__ atom_types, const float* __restrict__ t,
    const float* __restrict__ w_latent, const float* __restrict__ b_latent)
{
    __shared__ int at[20];
    int g = blockIdx.x, c = threadIdx.x;
    if (c < 20) at[c] = atom_types[g * 20 + c];
    float tl = b_latent[c];
    const float* tg = t + g * 256;
#pragma unroll 4
    for (int k = 0; k < 256; ++k)
        tl = fmaf(tg[k], w_latent[(128 + k) * 128 + c], tl);
    __syncthreads();
#pragma unroll
    for (int n = 0; n < 20; ++n)
        g_h[(g * 20 + n) * H_DIM + c] = g_embT[at[n] * 128 + c] + tl;
}

// ---------------- tensor nodeside: hs|hd = h @ W1[:256] ----------------
#define NSA 0                      // A 32*272 = 8704
#define NSB 8704                   // B 256*272 = 69632
#define NS_TOT 78336

__global__ __launch_bounds__(256, 2) void k_nodeside_t(
    int L, const float* __restrict__ ew1, const float* __restrict__ eb1)
{
    extern __shared__ char sm[];
    int g = blockIdx.x, tid = threadIdx.x;
    int w = tid >> 5, lane = tid & 31;
    int gq = lane >> 2, tig = lane & 3;

    if (tid < 128) {
        float lt = eb1[tid];
#pragma unroll
        for (int j = 0; j < 9; ++j)
            lt += g_latip[g * 9 + j] * ew1[(256 + j) * H_DIM + tid];
        g_latterm[g * H_DIM + tid] = lt;
    }
    for (int idx = tid; idx < 1280; idx += 256) {
        int r = idx >> 6, c2 = idx & 63;
        const float* src = g_h + g * 2560 + r * 128 + c2 * 2;
        *(u32*)(sm + NSA + r * 272 + c2 * 4) = pack_h2(src[0], src[1]);
    }
    for (int idx = tid; idx < 768; idx += 256) {
        int r = 20 + (idx >> 6), c2 = idx & 63;
        *(u32*)(sm + NSA + r * 272 + c2 * 4) = 0;
    }
    {
        const u32* src = (const u32*)(g_w1n + L * 32768);
        for (int idx = tid; idx < 16384; idx += 256) {
            int n = idx >> 6, k2 = idx & 63;
            *(u32*)(sm + NSB + n * 272 + k2 * 4) = src[idx];
        }
    }
    __syncthreads();

    int mt = w & 1;
    int nb = (w >> 1) * 8;
    float acc[8][4];
#pragma unroll
    for (int j = 0; j < 8; ++j)
        acc[j][0] = acc[j][1] = acc[j][2] = acc[j][3] = 0.f;
#pragma unroll
    for (int ks = 0; ks < 8; ++ks) {
        int kc = ks * 16 + 2 * tig;
        u32 ah[4];
        const char* Ab = sm + NSA + (mt * 16) * 272;
        ah[0] = *(const u32*)(Ab + gq * 272 + kc * 2);
        ah[1] = *(const u32*)(Ab + (gq + 8) * 272 + kc * 2);
        ah[2] = *(const u32*)(Ab + gq * 272 + (kc + 8) * 2);
        ah[3] = *(const u32*)(Ab + (gq + 8) * 272 + (kc + 8) * 2);
#pragma unroll
        for (int j = 0; j < 8; ++j) {
            const char* bh = sm + NSB + ((nb + j) * 8 + gq) * 272 + kc * 2;
            mma_f16(acc[j], ah, *(const u32*)bh, *(const u32*)(bh + 16));
        }
    }
    int rowA = mt * 16 + gq, rowB = rowA + 8;
#pragma unroll
    for (int j = 0; j < 8; ++j) {
        int n = (nb + j) * 8 + 2 * tig;
        float* dA = (n < 128) ? (g_hs + g * 2560 + rowA * 128 + n)
                              : (g_hd + g * 2560 + rowA * 128 + n - 128);
        float* dB = (n < 128) ? (g_hs + g * 2560 + rowB * 128 + n)
                              : (g_hd + g * 2560 + rowB * 128 + n - 128);
        if (rowA < 20) *(float2*)dA = make_float2(acc[j][0], acc[j][1]);
        if (rowB < 20) *(float2*)dB = make_float2(acc[j][2], acc[j][3]);
    }
}

// ---------------- tensor (mma.sync fp16) edge kernel ----------------
#define SW1 0           // W1d [128][72 halves] 18432
#define SW2 18432       // W2 [128][136] 34816
#define SAW 53248       // 16 warps x 4352
#define SHS 122880
#define SHD 133120
#define SLAT 143360
#define SB2 143872
#define SPART 144384    // [25][2][128] f32 = 25600
#define SM_TOT 169984

__global__ __launch_bounds__(512, 1) void k_edge_m(
    int L, const float* __restrict__ eb2)
{
    extern __shared__ char sm[];
    int tid = threadIdx.x, g0 = blockIdx.x;
    int w = tid >> 5, lane = tid & 31;
    int gq = lane >> 2, tig = lane & 3;

    {
        const u32* src = (const u32*)(g_w1d + L * 8192);
        for (int idx = tid; idx < 4096; idx += 512) {
            int n = idx >> 5, k2 = idx & 31;
            *(u32*)(sm + SW1 + n * 144 + k2 * 4) = src[idx];
        }
    }
    {
        const u32* src = (const u32*)(g_w2 + L * 16384);
        for (int idx = tid; idx < 8192; idx += 512) {
            int n = idx >> 6, k2 = idx & 63;
            *(u32*)(sm + SW2 + n * 272 + k2 * 4) = src[idx];
        }
    }
    float* hs = (float*)(sm + SHS);
    float* hd = (float*)(sm + SHD);
    for (int i = tid; i < 2560; i += 512) {
        hs[i] = g_hs[g0 * 2560 + i];
        hd[i] = g_hd[g0 * 2560 + i];
    }
    if (tid < 128) {
        ((float*)(sm + SLAT))[tid] = g_latterm[g0 * H_DIM + tid];
        ((float*)(sm + SB2))[tid] = eb2[tid];
    }
    __syncthreads();

    char* AB = sm + SAW + w * 4352;
    float* lat = (float*)(sm + SLAT);
    float* b2 = (float*)(sm + SB2);
    float* part = (float*)(sm + SPART);

    for (int tt = w; tt < 25; tt += 16) {
        int e0 = tt * 16;
        {
            const uint4* sH = (const uint4*)(g_disH + ((size_t)g0 * 400 + e0) * 64);
#pragma unroll
            for (int q = 0; q < 4; ++q) {
                int idx = lane + q * 32;
                int row = idx >> 3, seg = idx & 7;
                *(uint4*)(AB + row * 144 + seg * 16) = sH[row * 8 + seg];
            }
        }
        __syncwarp();

        // ---- GEMM1: dis[16,64] @ W1d[64,128] ----
        float acc[16][4];
#pragma unroll
        for (int j = 0; j < 16; ++j)
            acc[j][0] = acc[j][1] = acc[j][2] = acc[j][3] = 0.f;
#pragma unroll
        for (int ks = 0; ks < 4; ++ks) {
            int kc = ks * 16 + 2 * tig;
            u32 ah[4];
            ah[0] = *(const u32*)(AB + gq * 144 + kc * 2);
            ah[1] = *(const u32*)(AB + (gq + 8) * 144 + kc * 2);
            ah[2] = *(const u32*)(AB + gq * 144 + (kc + 8) * 2);
            ah[3] = *(const u32*)(AB + (gq + 8) * 144 + (kc + 8) * 2);
#pragma unroll
            for (int j = 0; j < 16; ++j) {
                const char* bh = sm + SW1 + ((j * 8 + gq) * 72 + kc) * 2;
                mma_f16(acc[j], ah, *(const u32*)bh, *(const u32*)(bh + 16));
            }
        }
        __syncwarp();

        // ---- epilogue A: + hs[src] + hd[dst] + lat, silu, fp16 -> A2 ----
        {
            int eA = e0 + gq, eB = e0 + gq + 8;
            int srcA = eA / 20, dstA = eA - srcA * 20;
            int srcB = eB / 20, dstB = eB - srcB * 20;
#pragma unroll
            for (int j = 0; j < 16; ++j) {
                int c0 = j * 8 + 2 * tig;
                float2 la = *(const float2*)&lat[c0];
                float2 hsA = *(const float2*)&hs[srcA * 128 + c0];
                float2 hdA = *(const float2*)&hd[dstA * 128 + c0];
                float2 hsB = *(const float2*)&hs[srcB * 128 + c0];
                float2 hdB = *(const float2*)&hd[dstB * 128 + c0];
                float x0 = silu_t(acc[j][0] + hsA.x + hdA.x + la.x);
                float x1 = silu_t(acc[j][1] + hsA.y + hdA.y + la.y);
                float x2 = silu_t(acc[j][2] + hsB.x + hdB.x + la.x);
                float x3 = silu_t(acc[j][3] + hsB.y + hdB.y + la.y);
                *(u32*)(AB + gq * 272 + c0 * 2) = pack_h2(x0, x1);
                *(u32*)(AB + (gq + 8) * 272 + c0 * 2) = pack_h2(x2, x3);
            }
        }
        __syncwarp();

        // ---- GEMM2: ef[16,128] @ W2[128,128] ----
        float acc2[16][4];
#pragma unroll
        for (int j = 0; j < 16; ++j)
            acc2[j][0] = acc2[j][1] = acc2[j][2] = acc2[j][3] = 0.f;
#pragma unroll
        for (int ks = 0; ks < 8; ++ks) {
            int kc = ks * 16 + 2 * tig;
            u32 ah[4];
            ah[0] = *(const u32*)(AB + gq * 272 + kc * 2);
            ah[1] = *(const u32*)(AB + (gq + 8) * 272 + kc * 2);
            ah[2] = *(const u32*)(AB + gq * 272 + (kc + 8) * 2);
            ah[3] = *(const u32*)(AB + (gq + 8) * 272 + (kc + 8) * 2);
#pragma unroll
            for (int j = 0; j < 16; ++j) {
                const char* bh = sm + SW2 + ((j * 8 + gq) * 136 + kc) * 2;
                mma_f16(acc2[j], ah, *(const u32*)bh, *(const u32*)(bh + 16));
            }
        }

        // ---- epilogue B: silu -> ef (two 64-col chunks), column partials ----
        {
            float* ef = (float*)AB;
            int sA = e0 / 20;
            int bnd = 20 * (sA + 1) - e0;
            if (bnd > 16) bnd = 16;
#pragma unroll
            for (int half = 0; half < 2; ++half) {
                __syncwarp();
#pragma unroll
                for (int j = half * 8; j < half * 8 + 8; ++j) {
                    int c0 = j * 8 + 2 * tig;
                    float2 bb = *(const float2*)&b2[c0];
                    float2 v0, v1;
                    v0.x = silu_t(acc2[j][0] + bb.x);
                    v0.y = silu_t(acc2[j][1] + bb.y);
                    v1.x = silu_t(acc2[j][2] + bb.x);
                    v1.y = silu_t(acc2[j][3] + bb.y);
                    int cl = c0 - half * 64;
                    *(float2*)&ef[gq * 68 + cl] = v0;
                    *(float2*)&ef[(gq + 8) * 68 + cl] = v1;
                }
                __syncwarp();
                int cl = 2 * lane;
                float2 p0 = make_float2(0.f, 0.f), p1 = make_float2(0.f, 0.f);
#pragma unroll
                for (int r = 0; r < 16; ++r) {
                    float2 v = *(const float2*)&ef[r * 68 + cl];
                    if (r < bnd) { p0.x += v.x; p0.y += v.y; }
                    else { p1.x += v.x; p1.y += v.y; }
                }
                *(float2*)&part[(tt * 2) * 128 + half * 64 + cl] = p0;
                *(float2*)&part[(tt * 2 + 1) * 128 + half * 64 + cl] = p1;
            }
        }
        __syncwarp();
    }
    __syncthreads();

    for (int idx = tid; idx < 2560; idx += 512) {
        int s = idx >> 7, c = idx & 127;
        int t0 = (20 * s) >> 4, t1 = (20 * s + 19) >> 4;
        float a = 0.f;
        for (int t = t0; t <= t1; ++t) {
            int sA = (16 * t) / 20;
            int sB = (16 * t + 15) / 20;
            if (sA == s) a += part[t * 256 + c];
            else if (sB == s) a += part[t * 256 + 128 + c];
        }
        g_agg[g0 * 2560 + idx] = a * 0.05f;
    }
}

// ---------------- tensor node MLP + residual ----------------
#define NMA1 0          // 32*528 = 16896
#define NMB1 16896      // 128*528 -> 84480
#define NMA2 84480      // 32*272 -> 93184
#define NMB2 93184      // 128*272 -> 128000
#define NM_TOT 128000

__global__ __launch_bounds__(256, 1) void k_nodemlp_t(
    int L, const float* __restrict__ nb1, const float* __restrict__ nb2)
{
    extern __shared__ char sm[];
    int g = blockIdx.x, tid = threadIdx.x;
    int w = tid >> 5, lane = tid & 31;
    int gq = lane >> 2, tig = lane & 3;

    for (int idx = tid; idx < 2560; idx += 256) {
        int r = idx >> 7, c2 = idx & 127;
        float a0, a1;
        if (c2 < 64) {
            const float* s = g_h + g * 2560 + r * 128 + c2 * 2;
            a0 = s[0]; a1 = s[1];
        } else {
            const float* s = g_agg + g * 2560 + r * 128 + (c2 - 64) * 2;
            a0 = s[0]; a1 = s[1];
        }
        *(u32*)(sm + NMA1 + r * 528 + c2 * 4) = pack_h2(a0, a1);
    }
    for (int idx = tid; idx < 1536; idx += 256) {
        int r = 20 + (idx >> 7), c2 = idx & 127;
        *(u32*)(sm + NMA1 + r * 528 + c2 * 4) = 0;
    }
    {
        const u32* src = (const u32*)(g_nw1 + L * 32768);
        for (int idx = tid; idx < 16384; idx += 256) {
            int n = idx >> 7, k2 = idx & 127;
            *(u32*)(sm + NMB1 + n * 528 + k2 * 4) = src[idx];
        }
        const u32* src2 = (const u32*)(g_nw2 + L * 16384);
        for (int idx = tid; idx < 8192; idx += 256) {
            int n = idx >> 6, k2 = idx & 63;
            *(u32*)(sm + NMB2 + n * 272 + k2 * 4) = src2[idx];
        }
    }
    __syncthreads();

    int mt = w & 1;
    int nb = (w >> 1) * 4;
    float acc[4][4];
#pragma unroll
    for (int j = 0; j < 4; ++j)
        acc[j][0] = acc[j][1] = acc[j][2] = acc[j][3] = 0.f;
#pragma unroll
    for (int ks = 0; ks < 16; ++ks) {
        int kc = ks * 16 + 2 * tig;
        u32 ah[4];
        const char* Ab = sm + NMA1 + (mt * 16) * 528;
        ah[0] = *(const u32*)(Ab + gq * 528 + kc * 2);
        ah[1] = *(const u32*)(Ab + (gq + 8) * 528 + kc * 2);
        ah[2] = *(const u32*)(Ab + gq * 528 + (kc + 8) * 2);
        ah[3] = *(const u32*)(Ab + (gq + 8) * 528 + (kc + 8) * 2);
#pragma unroll
        for (int j = 0; j < 4; ++j) {
            const char* bh = sm + NMB1 + ((nb + j) * 8 + gq) * 528 + kc * 2;
            mma_f16(acc[j], ah, *(const u32*)bh, *(const u32*)(bh + 16));
        }
    }
    {
        int rA = mt * 16 + gq;
#pragma unroll
        for (int j = 0; j < 4; ++j) {
            int c0 = (nb + j) * 8 + 2 * tig;
            float bb0 = __ldg(nb1 + c0), bb1 = __ldg(nb1 + c0 + 1);
            *(u32*)(sm + NMA2 + rA * 272 + c0 * 2) =
                pack_h2(siluf(acc[j][0] + bb0), siluf(acc[j][1] + bb1));
            *(u32*)(sm + NMA2 + (rA + 8) * 272 + c0 * 2) =
                pack_h2(siluf(acc[j][2] + bb0), siluf(acc[j][3] + bb1));
        }
    }
    __syncthreads();

    float acc2[4][4];
#pragma unroll
    for (int j = 0; j < 4; ++j)
        acc2[j][0] = acc2[j][1] = acc2[j][2] = acc2[j][3] = 0.f;
#pragma unroll
    for (int ks = 0; ks < 8; ++ks) {
        int kc = ks * 16 + 2 * tig;
        u32 ah[4];
        const char* Ab = sm + NMA2 + (mt * 16) * 272;
        ah[0] = *(const u32*)(Ab + gq * 272 + kc * 2);
        ah[1] = *(const u32*)(Ab + (gq + 8) * 272 + kc * 2);
        ah[2] = *(const u32*)(Ab + gq * 272 + (kc + 8) * 2);
        ah[3] = *(const u32*)(Ab + (gq + 8) * 272 + (kc + 8) * 2);
#pragma unroll
        for (int j = 0; j < 4; ++j) {
            const char* bh = sm + NMB2 + ((nb + j) * 8 + gq) * 136 * 2 + kc * 2;
            mma_f16(acc2[j], ah, *(const u32*)bh, *(const u32*)(bh + 16));
        }
    }
    {
        int rA = mt * 16 + gq, rB = rA + 8;
#pragma unroll
        for (int j = 0; j < 4; ++j) {
            int c0 = (nb + j) * 8 + 2 * tig;
            float bb0 = __ldg(nb2 + c0), bb1 = __ldg(nb2 + c0 + 1);
            if (rA < 20) {
                float* d = g_h + g * 2560 + rA * 128 + c0;
                float2 o = *(float2*)d;
                o.x += siluf(acc2[j][0] + bb0);
                o.y += siluf(acc2[j][1] + bb1);
                *(float2*)d = o;
            }
            if (rB < 20) {
                float* d = g_h + g * 2560 + rB * 128 + c0;
                float2 o = *(float2*)d;
                o.x += siluf(acc2[j][2] + bb0);
                o.y += siluf(acc2[j][3] + bb1);
                *(float2*)d = o;
            }
        }
    }
}

// ---------------- output heads ----------------
__global__ __launch_bounds__(128) void k_final(
    const float* __restrict__ lattices, const float* __restrict__ coord_w,
    const float* __restrict__ lattice_w, float* __restrict__ out)
{
    __shared__ __align__(16) float hT[128 * 20];
    __shared__ float gf[128];
    __shared__ float pre[9];
    int g = blockIdx.x, tid = threadIdx.x;
    for (int n = 0; n < 20; ++n)
        hT[tid * 20 + n] = g_h[(g * 20 + n) * H_DIM + tid];
    __syncthreads();
    float s = 0.f;
#pragma unroll
    for (int n = 0; n < 20; ++n) s += hT[tid * 20 + n];
    gf[tid] = s * 0.05f;
    __syncthreads();
    if (tid < 9) {
        float acc = 0.f;
        for (int k = 0; k < 128; ++k) acc += gf[k] * lattice_w[k * 9 + tid];
        pre[tid] = acc;
    }
    __syncthreads();
    if (tid < 9) {
        int i = tid / 3, kk = tid % 3;
        float v = 0.f;
#pragma unroll
        for (int j = 0; j < 3; ++j)
            v += pre[i * 3 + j] * lattices[g * 9 + j * 3 + kk];
        out[g * 9 + tid] = v;
    }
    if (tid < 60) {
        int n = tid / 3, c = tid % 3;
        float acc = 0.f;
        for (int k = 0; k < 128; ++k) acc += hT[k * 20 + n] * coord_w[k * 3 + c];
        out[G_CNT * 9 + (g * 20 + n) * 3 + c] = acc;
    }
}

// ---------------- launch ----------------
extern "C" void kernel_launch(void* const* d_in, const int* in_sizes, int n_in,
                              void* d_out, int out_size) {
    const int*   atom_types = (const int*)d_in[0];
    const float* frac       = (const float*)d_in[1];
    const float* lattices   = (const float*)d_in[2];
    const float* t          = (const float*)d_in[3];
    const float* emb_table  = (const float*)d_in[7];
    const float* w_latent   = (const float*)d_in[8];
    const float* b_latent   = (const float*)d_in[9];
    const float* ew1        = (const float*)d_in[10];
    const float* eb1        = (const float*)d_in[11];
    const float* ew2        = (const float*)d_in[12];
    const float* eb2        = (const float*)d_in[13];
    const float* nw1        = (const float*)d_in[14];
    const float* nb1        = (const float*)d_in[15];
    const float* nw2        = (const float*)d_in[16];
    const float* nb2        = (const float*)d_in[17];
    const float* coord_w    = (const float*)d_in[18];
    const float* lattice_w  = (const float*)d_in[19];
    float* out = (float*)d_out;

    cudaFuncSetAttribute(k_edge_m, cudaFuncAttributeMaxDynamicSharedMemorySize, SM_TOT);
    cudaFuncSetAttribute(k_nodemlp_t, cudaFuncAttributeMaxDynamicSharedMemorySize, NM_TOT);
    cudaFuncSetAttribute(k_nodeside_t, cudaFuncAttributeMaxDynamicSharedMemorySize, NS_TOT);

    k_prep<<<(NLAYER * 106496 + 255) / 256, 256>>>(ew1, ew2, nw1, nw2);
    k_prep_emb<<<100, 128>>>(emb_table, w_latent);
    k_latip<<<G_CNT, 32>>>(lattices);
    k_embed<<<G_CNT, 128>>>(atom_types, t, w_latent, b_latent);
    k_dis<<<E_CNT / 128, 128>>>(frac);
    for (int i = 0; i < NLAYER; ++i) {
        k_nodeside_t<<<G_CNT, 256, NS_TOT>>>(i, ew1 + i * 325 * 128, eb1 + i * 128);
        k_edge_m<<<G_CNT, 512, SM_TOT>>>(i, eb2 + i * 128);
        k_nodemlp_t<<<G_CNT, 256, NM_TOT>>>(i, nb1 + i * 128, nb2 + i * 128);
    }
    k_final<<<G_CNT, 128>>>(lattices, coord_w, lattice_w, out);
}

// round 9
// speedup vs baseline: 1.2696x; 1.2696x over previous
#include <cuda_runtime.h>
#include <cuda_bf16.h>
#include <cuda_fp16.h>
#include <math.h>
#include <stdint.h>

#define G_CNT 1024
#define A_CNT 20
#define N_CNT (G_CNT * A_CNT)          // 20480
#define E_CNT (G_CNT * A_CNT * A_CNT)  // 409600
#define H_DIM 128
#define NLAYER 4

typedef unsigned long long u64;
typedef unsigned int u32;
typedef unsigned short u16;

// ---------------- scratch (device globals) ----------------
__device__ float g_h[N_CNT * H_DIM];
__device__ float g_hs[N_CNT * H_DIM];
__device__ float g_hd[N_CNT * H_DIM];
__device__ float g_agg[N_CNT * H_DIM];
__device__ float g_latip[G_CNT * 9];
__device__ float g_latterm[G_CNT * H_DIM];
__device__ float g_embT[100 * H_DIM];            // emb_table @ w_latent[:128]
__device__ u16 g_disH[(size_t)E_CNT * 64];       // dis fp16 [edge][64]
// fp16 weights, consumer-ready K-major [n][k]
__device__ u16 g_w1d[NLAYER * 128 * 64];
__device__ u16 g_w1n[NLAYER * 256 * 128];
__device__ u16 g_w2[NLAYER * 128 * 128];
__device__ u16 g_nw1[NLAYER * 128 * 256];
__device__ u16 g_nw2[NLAYER * 128 * 128];

// silu via EX2 + RCP (both fast MUFU on sm_103a; tanh.approx is NOT -> R8 regression)
__device__ __forceinline__ float siluf(float x) {
    return __fdividef(x, 1.0f + __expf(-x));
}
__device__ __forceinline__ u16 h_rn(float x) {
    return __half_as_ushort(__float2half_rn(x));
}
__device__ __forceinline__ u32 pack_h2(float a, float b) {
    __half2 hh = __floats2half2_rn(a, b);
    return *(u32*)&hh;
}

__device__ __forceinline__ void mma_f16(float c[4], const u32 a[4], u32 b0, u32 b1) {
    asm volatile(
        "mma.sync.aligned.m16n8k16.row.col.f32.f16.f16.f32 "
        "{%0,%1,%2,%3}, {%4,%5,%6,%7}, {%8,%9}, {%0,%1,%2,%3};"
        : "+f"(c[0]), "+f"(c[1]), "+f"(c[2]), "+f"(c[3])
        : "r"(a[0]), "r"(a[1]), "r"(a[2]), "r"(a[3]), "r"(b0), "r"(b1));
}

// ---------------- weight prep: fp32 -> fp16 K-major, once ----------------
__global__ __launch_bounds__(256) void k_prep(
    const float* __restrict__ ew1, const float* __restrict__ ew2,
    const float* __restrict__ nw1, const float* __restrict__ nw2)
{
    int i = blockIdx.x * 256 + threadIdx.x;
    if (i >= NLAYER * 106496) return;
    int L = i / 106496, j = i % 106496;
    const float* e1 = ew1 + L * 325 * 128;
    const float* e2 = ew2 + L * 128 * 128;
    const float* n1 = nw1 + L * 256 * 128;
    const float* n2 = nw2 + L * 128 * 128;
    if (j < 8192) {                       // w1d [n=128][k=64], pad k>=60
        int n = j >> 6, k = j & 63;
        float v = (k < 60) ? e1[(265 + k) * 128 + n] : 0.f;
        g_w1d[L * 8192 + j] = h_rn(v);
    } else if (j < 40960) {               // w1n [n=256][k=128]
        int jj = j - 8192;
        int n = jj >> 7, k = jj & 127;
        float v = (n < 128) ? e1[k * 128 + n] : e1[(128 + k) * 128 + (n - 128)];
        g_w1n[L * 32768 + jj] = h_rn(v);
    } else if (j < 57344) {               // w2 [n=128][k=128]
        int jj = j - 40960;
        int n = jj >> 7, k = jj & 127;
        g_w2[L * 16384 + jj] = h_rn(e2[k * 128 + n]);
    } else if (j < 90112) {               // nw1 [n=128][k=256]
        int jj = j - 57344;
        int n = jj >> 8, k = jj & 255;
        g_nw1[L * 32768 + jj] = h_rn(n1[k * 128 + n]);
    } else {                              // nw2 [n=128][k=128]
        int jj = j - 90112;
        int n = jj >> 7, k = jj & 127;
        g_nw2[L * 16384 + jj] = h_rn(n2[k * 128 + n]);
    }
}

// ---------------- embT[a] = emb_table[a] @ w_latent[:128] ----------------
__global__ __launch_bounds__(128) void k_prep_emb(
    const float* __restrict__ emb_table, const float* __restrict__ w_latent)
{
    int a = blockIdx.x, c = threadIdx.x;
    float s = 0.f;
#pragma unroll 4
    for (int k = 0; k < 128; ++k)
        s = fmaf(emb_table[a * 128 + k], w_latent[k * 128 + c], s);
    g_embT[a * 128 + c] = s;
}

// ---------------- lat_ip = L @ L^T ----------------
__global__ void k_latip(const float* __restrict__ lattices) {
    int g = blockIdx.x, tid = threadIdx.x;
    if (tid < 9) {
        int i = tid / 3, k = tid % 3;
        float s = 0.f;
#pragma unroll
        for (int j = 0; j < 3; ++j)
            s += lattices[g * 9 + i * 3 + j] * lattices[g * 9 + k * 3 + j];
        g_latip[g * 9 + tid] = s;
    }
}

// ---------------- dis embedding -> fp16, [e][64] ----------------
// smem row stride 33 u32: conflict-free stores and loads
__global__ __launch_bounds__(128) void k_dis(const float* __restrict__ fc) {
    __shared__ u32 hiS[128 * 33];
    int tid = threadIdx.x;
    size_t e0 = (size_t)blockIdx.x * 128;
    int e = (int)e0 + tid;
    int g = e / 400, r = e % 400;
    int src = g * 20 + r / 20;
    int dst = g * 20 + r % 20;
    u16* hrow = (u16*)(hiS + tid * 33);
#pragma unroll
    for (int c = 0; c < 3; ++c) {
        float d = fc[dst * 3 + c] - fc[src * 3 + c];
        d -= floorf(d);
        float s1, c1;
        sincospif(2.0f * d, &s1, &c1);
        float s = 0.f, co = 1.f;
        hrow[c * 10] = 0;
        hrow[30 + c * 10] = h_rn(1.f);
#pragma unroll
        for (int f = 1; f < 10; ++f) {
            float ns = s * c1 + co * s1;
            float nc = co * c1 - s * s1;
            s = ns; co = nc;
            hrow[c * 10 + f] = h_rn(s);
            hrow[30 + c * 10 + f] = h_rn(co);
        }
    }
#pragma unroll
    for (int k = 60; k < 64; ++k) hrow[k] = 0;
    __syncthreads();
    u32* gh = (u32*)g_disH + e0 * 32;
    for (int i = tid; i < 4096; i += 128)
        gh[i] = hiS[(i >> 5) * 33 + (i & 31)];
}

// ---------------- node embedding: gather(embT) + per-graph t-latent ------
__global__ __launch_bounds__(128) void k_embed(
    const int* __restrict__ atom_types, const float* __restrict__ t,
    const float* __restrict__ w_latent, const float* __restrict__ b_latent)
{
    __shared__ int at[20];
    int g = blockIdx.x, c = threadIdx.x;
    if (c < 20) at[c] = atom_types[g * 20 + c];
    float tl = b_latent[c];
    const float* tg = t + g * 256;
#pragma unroll 4
    for (int k = 0; k < 256; ++k)
        tl = fmaf(tg[k], w_latent[(128 + k) * 128 + c], tl);
    __syncthreads();
#pragma unroll
    for (int n = 0; n < 20; ++n)
        g_h[(g * 20 + n) * H_DIM + c] = g_embT[at[n] * 128 + c] + tl;
}

// ---------------- tensor nodeside: hs|hd = h @ W1[:256] ----------------
#define NSA 0                      // A 32*272 = 8704
#define NSB 8704                   // B 256*272 = 69632
#define NS_TOT 78336

__global__ __launch_bounds__(256, 2) void k_nodeside_t(
    int L, const float* __restrict__ ew1, const float* __restrict__ eb1)
{
    extern __shared__ char sm[];
    int g = blockIdx.x, tid = threadIdx.x;
    int w = tid >> 5, lane = tid & 31;
    int gq = lane >> 2, tig = lane & 3;

    if (tid < 128) {
        float lt = eb1[tid];
#pragma unroll
        for (int j = 0; j < 9; ++j)
            lt += g_latip[g * 9 + j] * ew1[(256 + j) * H_DIM + tid];
        g_latterm[g * H_DIM + tid] = lt;
    }
    for (int idx = tid; idx < 1280; idx += 256) {
        int r = idx >> 6, c2 = idx & 63;
        const float* src = g_h + g * 2560 + r * 128 + c2 * 2;
        *(u32*)(sm + NSA + r * 272 + c2 * 4) = pack_h2(src[0], src[1]);
    }
    for (int idx = tid; idx < 768; idx += 256) {
        int r = 20 + (idx >> 6), c2 = idx & 63;
        *(u32*)(sm + NSA + r * 272 + c2 * 4) = 0;
    }
    {
        const u32* src = (const u32*)(g_w1n + L * 32768);
        for (int idx = tid; idx < 16384; idx += 256) {
            int n = idx >> 6, k2 = idx & 63;
            *(u32*)(sm + NSB + n * 272 + k2 * 4) = src[idx];
        }
    }
    __syncthreads();

    int mt = w & 1;
    int nb = (w >> 1) * 8;
    float acc[8][4];
#pragma unroll
    for (int j = 0; j < 8; ++j)
        acc[j][0] = acc[j][1] = acc[j][2] = acc[j][3] = 0.f;
#pragma unroll
    for (int ks = 0; ks < 8; ++ks) {
        int kc = ks * 16 + 2 * tig;
        u32 ah[4];
        const char* Ab = sm + NSA + (mt * 16) * 272;
        ah[0] = *(const u32*)(Ab + gq * 272 + kc * 2);
        ah[1] = *(const u32*)(Ab + (gq + 8) * 272 + kc * 2);
        ah[2] = *(const u32*)(Ab + gq * 272 + (kc + 8) * 2);
        ah[3] = *(const u32*)(Ab + (gq + 8) * 272 + (kc + 8) * 2);
#pragma unroll
        for (int j = 0; j < 8; ++j) {
            const char* bh = sm + NSB + ((nb + j) * 8 + gq) * 272 + kc * 2;
            mma_f16(acc[j], ah, *(const u32*)bh, *(const u32*)(bh + 16));
        }
    }
    int rowA = mt * 16 + gq, rowB = rowA + 8;
#pragma unroll
    for (int j = 0; j < 8; ++j) {
        int n = (nb + j) * 8 + 2 * tig;
        float* dA = (n < 128) ? (g_hs + g * 2560 + rowA * 128 + n)
                              : (g_hd + g * 2560 + rowA * 128 + n - 128);
        float* dB = (n < 128) ? (g_hs + g * 2560 + rowB * 128 + n)
                              : (g_hd + g * 2560 + rowB * 128 + n - 128);
        if (rowA < 20) *(float2*)dA = make_float2(acc[j][0], acc[j][1]);
        if (rowB < 20) *(float2*)dB = make_float2(acc[j][2], acc[j][3]);
    }
}

// ---------------- tensor (mma.sync fp16) edge kernel ----------------
#define SW1 0           // W1d [128][72 halves] 18432
#define SW2 18432       // W2 [128][136] 34816
#define SAW 53248       // 16 warps x 4352
#define SHS 122880
#define SHD 133120
#define SLAT 143360
#define SB2 143872
#define SPART 144384    // [25][2][128] f32 = 25600
#define SM_TOT 169984

__global__ __launch_bounds__(512, 1) void k_edge_m(
    int L, const float* __restrict__ eb2)
{
    extern __shared__ char sm[];
    int tid = threadIdx.x, g0 = blockIdx.x;
    int w = tid >> 5, lane = tid & 31;
    int gq = lane >> 2, tig = lane & 3;

    {
        const u32* src = (const u32*)(g_w1d + L * 8192);
        for (int idx = tid; idx < 4096; idx += 512) {
            int n = idx >> 5, k2 = idx & 31;
            *(u32*)(sm + SW1 + n * 144 + k2 * 4) = src[idx];
        }
    }
    {
        const u32* src = (const u32*)(g_w2 + L * 16384);
        for (int idx = tid; idx < 8192; idx += 512) {
            int n = idx >> 6, k2 = idx & 63;
            *(u32*)(sm + SW2 + n * 272 + k2 * 4) = src[idx];
        }
    }
    float* hs = (float*)(sm + SHS);
    float* hd = (float*)(sm + SHD);
    for (int i = tid; i < 2560; i += 512) {
        hs[i] = g_hs[g0 * 2560 + i];
        hd[i] = g_hd[g0 * 2560 + i];
    }
    if (tid < 128) {
        ((float*)(sm + SLAT))[tid] = g_latterm[g0 * H_DIM + tid];
        ((float*)(sm + SB2))[tid] = eb2[tid];
    }
    __syncthreads();

    char* AB = sm + SAW + w * 4352;
    float* lat = (float*)(sm + SLAT);
    float* b2 = (float*)(sm + SB2);
    float* part = (float*)(sm + SPART);

    for (int tt = w; tt < 25; tt += 16) {
        int e0 = tt * 16;
        {
            const uint4* sH = (const uint4*)(g_disH + ((size_t)g0 * 400 + e0) * 64);
#pragma unroll
            for (int q = 0; q < 4; ++q) {
                int idx = lane + q * 32;
                int row = idx >> 3, seg = idx & 7;
                *(uint4*)(AB + row * 144 + seg * 16) = sH[row * 8 + seg];
            }
        }
        __syncwarp();

        // ---- GEMM1: dis[16,64] @ W1d[64,128] ----
        float acc[16][4];
#pragma unroll
        for (int j = 0; j < 16; ++j)
            acc[j][0] = acc[j][1] = acc[j][2] = acc[j][3] = 0.f;
#pragma unroll
        for (int ks = 0; ks < 4; ++ks) {
            int kc = ks * 16 + 2 * tig;
            u32 ah[4];
            ah[0] = *(const u32*)(AB + gq * 144 + kc * 2);
            ah[1] = *(const u32*)(AB + (gq + 8) * 144 + kc * 2);
            ah[2] = *(const u32*)(AB + gq * 144 + (kc + 8) * 2);
            ah[3] = *(const u32*)(AB + (gq + 8) * 144 + (kc + 8) * 2);
#pragma unroll
            for (int j = 0; j < 16; ++j) {
                const char* bh = sm + SW1 + ((j * 8 + gq) * 72 + kc) * 2;
                mma_f16(acc[j], ah, *(const u32*)bh, *(const u32*)(bh + 16));
            }
        }
        __syncwarp();

        // ---- epilogue A: + hs[src] + hd[dst] + lat, silu, fp16 -> A2 ----
        {
            int eA = e0 + gq, eB = e0 + gq + 8;
            int srcA = eA / 20, dstA = eA - srcA * 20;
            int srcB = eB / 20, dstB = eB - srcB * 20;
#pragma unroll
            for (int j = 0; j < 16; ++j) {
                int c0 = j * 8 + 2 * tig;
                float2 la = *(const float2*)&lat[c0];
                float2 hsA = *(const float2*)&hs[srcA * 128 + c0];
                float2 hdA = *(const float2*)&hd[dstA * 128 + c0];
                float2 hsB = *(const float2*)&hs[srcB * 128 + c0];
                float2 hdB = *(const float2*)&hd[dstB * 128 + c0];
                float x0 = siluf(acc[j][0] + hsA.x + hdA.x + la.x);
                float x1 = siluf(acc[j][1] + hsA.y + hdA.y + la.y);
                float x2 = siluf(acc[j][2] + hsB.x + hdB.x + la.x);
                float x3 = siluf(acc[j][3] + hsB.y + hdB.y + la.y);
                *(u32*)(AB + gq * 272 + c0 * 2) = pack_h2(x0, x1);
                *(u32*)(AB + (gq + 8) * 272 + c0 * 2) = pack_h2(x2, x3);
            }
        }
        __syncwarp();

        // ---- GEMM2: ef[16,128] @ W2[128,128] ----
        float acc2[16][4];
#pragma unroll
        for (int j = 0; j < 16; ++j)
            acc2[j][0] = acc2[j][1] = acc2[j][2] = acc2[j][3] = 0.f;
#pragma unroll
        for (int ks = 0; ks < 8; ++ks) {
            int kc = ks * 16 + 2 * tig;
            u32 ah[4];
            ah[0] = *(const u32*)(AB + gq * 272 + kc * 2);
            ah[1] = *(const u32*)(AB + (gq + 8) * 272 + kc * 2);
            ah[2] = *(const u32*)(AB + gq * 272 + (kc + 8) * 2);
            ah[3] = *(const u32*)(AB + (gq + 8) * 272 + (kc + 8) * 2);
#pragma unroll
            for (int j = 0; j < 16; ++j) {
                const char* bh = sm + SW2 + ((j * 8 + gq) * 136 + kc) * 2;
                mma_f16(acc2[j], ah, *(const u32*)bh, *(const u32*)(bh + 16));
            }
        }

        // ---- epilogue B: silu -> ef (two 64-col chunks), column partials ----
        {
            float* ef = (float*)AB;
            int sA = e0 / 20;
            int bnd = 20 * (sA + 1) - e0;
            if (bnd > 16) bnd = 16;
#pragma unroll
            for (int half = 0; half < 2; ++half) {
                __syncwarp();
#pragma unroll
                for (int j = half * 8; j < half * 8 + 8; ++j) {
                    int c0 = j * 8 + 2 * tig;
                    float2 bb = *(const float2*)&b2[c0];
                    float2 v0, v1;
                    v0.x = siluf(acc2[j][0] + bb.x);
                    v0.y = siluf(acc2[j][1] + bb.y);
                    v1.x = siluf(acc2[j][2] + bb.x);
                    v1.y = siluf(acc2[j][3] + bb.y);
                    int cl = c0 - half * 64;
                    *(float2*)&ef[gq * 68 + cl] = v0;
                    *(float2*)&ef[(gq + 8) * 68 + cl] = v1;
                }
                __syncwarp();
                int cl = 2 * lane;
                float2 p0 = make_float2(0.f, 0.f), p1 = make_float2(0.f, 0.f);
#pragma unroll
                for (int r = 0; r < 16; ++r) {
                    float2 v = *(const float2*)&ef[r * 68 + cl];
                    if (r < bnd) { p0.x += v.x; p0.y += v.y; }
                    else { p1.x += v.x; p1.y += v.y; }
                }
                *(float2*)&part[(tt * 2) * 128 + half * 64 + cl] = p0;
                *(float2*)&part[(tt * 2 + 1) * 128 + half * 64 + cl] = p1;
            }
        }
        __syncwarp();
    }
    __syncthreads();

    for (int idx = tid; idx < 2560; idx += 512) {
        int s = idx >> 7, c = idx & 127;
        int t0 = (20 * s) >> 4, t1 = (20 * s + 19) >> 4;
        float a = 0.f;
        for (int t = t0; t <= t1; ++t) {
            int sA = (16 * t) / 20;
            int sB = (16 * t + 15) / 20;
            if (sA == s) a += part[t * 256 + c];
            else if (sB == s) a += part[t * 256 + 128 + c];
        }
        g_agg[g0 * 2560 + idx] = a * 0.05f;
    }
}

// ---------------- tensor node MLP + residual ----------------
#define NMA1 0          // 32*528 = 16896
#define NMB1 16896      // 128*528 -> 84480
#define NMA2 84480      // 32*272 -> 93184
#define NMB2 93184      // 128*272 -> 128000
#define NM_TOT 128000

__global__ __launch_bounds__(256, 1) void k_nodemlp_t(
    int L, const float* __restrict__ nb1, const float* __restrict__ nb2)
{
    extern __shared__ char sm[];
    int g = blockIdx.x, tid = threadIdx.x;
    int w = tid >> 5, lane = tid & 31;
    int gq = lane >> 2, tig = lane & 3;

    for (int idx = tid; idx < 2560; idx += 256) {
        int r = idx >> 7, c2 = idx & 127;
        float a0, a1;
        if (c2 < 64) {
            const float* s = g_h + g * 2560 + r * 128 + c2 * 2;
            a0 = s[0]; a1 = s[1];
        } else {
            const float* s = g_agg + g * 2560 + r * 128 + (c2 - 64) * 2;
            a0 = s[0]; a1 = s[1];
        }
        *(u32*)(sm + NMA1 + r * 528 + c2 * 4) = pack_h2(a0, a1);
    }
    for (int idx = tid; idx < 1536; idx += 256) {
        int r = 20 + (idx >> 7), c2 = idx & 127;
        *(u32*)(sm + NMA1 + r * 528 + c2 * 4) = 0;
    }
    {
        const u32* src = (const u32*)(g_nw1 + L * 32768);
        for (int idx = tid; idx < 16384; idx += 256) {
            int n = idx >> 7, k2 = idx & 127;
            *(u32*)(sm + NMB1 + n * 528 + k2 * 4) = src[idx];
        }
        const u32* src2 = (const u32*)(g_nw2 + L * 16384);
        for (int idx = tid; idx < 8192; idx += 256) {
            int n = idx >> 6, k2 = idx & 63;
            *(u32*)(sm + NMB2 + n * 272 + k2 * 4) = src2[idx];
        }
    }
    __syncthreads();

    int mt = w & 1;
    int nb = (w >> 1) * 4;
    float acc[4][4];
#pragma unroll
    for (int j = 0; j < 4; ++j)
        acc[j][0] = acc[j][1] = acc[j][2] = acc[j][3] = 0.f;
#pragma unroll
    for (int ks = 0; ks < 16; ++ks) {
        int kc = ks * 16 + 2 * tig;
        u32 ah[4];
        const char* Ab = sm + NMA1 + (mt * 16) * 528;
        ah[0] = *(const u32*)(Ab + gq * 528 + kc * 2);
        ah[1] = *(const u32*)(Ab + (gq + 8) * 528 + kc * 2);
        ah[2] = *(const u32*)(Ab + gq * 528 + (kc + 8) * 2);
        ah[3] = *(const u32*)(Ab + (gq + 8) * 528 + (kc + 8) * 2);
#pragma unroll
        for (int j = 0; j < 4; ++j) {
            const char* bh = sm + NMB1 + ((nb + j) * 8 + gq) * 528 + kc * 2;
            mma_f16(acc[j], ah, *(const u32*)bh, *(const u32*)(bh + 16));
        }
    }
    {
        int rA = mt * 16 + gq;
#pragma unroll
        for (int j = 0; j < 4; ++j) {
            int c0 = (nb + j) * 8 + 2 * tig;
            float bb0 = __ldg(nb1 + c0), bb1 = __ldg(nb1 + c0 + 1);
            *(u32*)(sm + NMA2 + rA * 272 + c0 * 2) =
                pack_h2(siluf(acc[j][0] + bb0), siluf(acc[j][1] + bb1));
            *(u32*)(sm + NMA2 + (rA + 8) * 272 + c0 * 2) =
                pack_h2(siluf(acc[j][2] + bb0), siluf(acc[j][3] + bb1));
        }
    }
    __syncthreads();

    float acc2[4][4];
#pragma unroll
    for (int j = 0; j < 4; ++j)
        acc2[j][0] = acc2[j][1] = acc2[j][2] = acc2[j][3] = 0.f;
#pragma unroll
    for (int ks = 0; ks < 8; ++ks) {
        int kc = ks * 16 + 2 * tig;
        u32 ah[4];
        const char* Ab = sm + NMA2 + (mt * 16) * 272;
        ah[0] = *(const u32*)(Ab + gq * 272 + kc * 2);
        ah[1] = *(const u32*)(Ab + (gq + 8) * 272 + kc * 2);
        ah[2] = *(const u32*)(Ab + gq * 272 + (kc + 8) * 2);
        ah[3] = *(const u32*)(Ab + (gq + 8) * 272 + (kc + 8) * 2);
#pragma unroll
        for (int j = 0; j < 4; ++j) {
            const char* bh = sm + NMB2 + ((nb + j) * 8 + gq) * 136 * 2 + kc * 2;
            mma_f16(acc2[j], ah, *(const u32*)bh, *(const u32*)(bh + 16));
        }
    }
    {
        int rA = mt * 16 + gq, rB = rA + 8;
#pragma unroll
        for (int j = 0; j < 4; ++j) {
            int c0 = (nb + j) * 8 + 2 * tig;
            float bb0 = __ldg(nb2 + c0), bb1 = __ldg(nb2 + c0 + 1);
            if (rA < 20) {
                float* d = g_h + g * 2560 + rA * 128 + c0;
                float2 o = *(float2*)d;
                o.x += siluf(acc2[j][0] + bb0);
                o.y += siluf(acc2[j][1] + bb1);
                *(float2*)d = o;
            }
            if (rB < 20) {
                float* d = g_h + g * 2560 + rB * 128 + c0;
                float2 o = *(float2*)d;
                o.x += siluf(acc2[j][2] + bb0);
                o.y += siluf(acc2[j][3] + bb1);
                *(float2*)d = o;
            }
        }
    }
}

// ---------------- output heads ----------------
__global__ __launch_bounds__(128) void k_final(
    const float* __restrict__ lattices, const float* __restrict__ coord_w,
    const float* __restrict__ lattice_w, float* __restrict__ out)
{
    __shared__ __align__(16) float hT[128 * 20];
    __shared__ float gf[128];
    __shared__ float pre[9];
    int g = blockIdx.x, tid = threadIdx.x;
    for (int n = 0; n < 20; ++n)
        hT[tid * 20 + n] = g_h[(g * 20 + n) * H_DIM + tid];
    __syncthreads();
    float s = 0.f;
#pragma unroll
    for (int n = 0; n < 20; ++n) s += hT[tid * 20 + n];
    gf[tid] = s * 0.05f;
    __syncthreads();
    if (tid < 9) {
        float acc = 0.f;
        for (int k = 0; k < 128; ++k) acc += gf[k] * lattice_w[k * 9 + tid];
        pre[tid] = acc;
    }
    __syncthreads();
    if (tid < 9) {
        int i = tid / 3, kk = tid % 3;
        float v = 0.f;
#pragma unroll
        for (int j = 0; j < 3; ++j)
            v += pre[i * 3 + j] * lattices[g * 9 + j * 3 + kk];
        out[g * 9 + tid] = v;
    }
    if (tid < 60) {
        int n = tid / 3, c = tid % 3;
        float acc = 0.f;
        for (int k = 0; k < 128; ++k) acc += hT[k * 20 + n] * coord_w[k * 3 + c];
        out[G_CNT * 9 + (g * 20 + n) * 3 + c] = acc;
    }
}

// ---------------- launch ----------------
extern "C" void kernel_launch(void* const* d_in, const int* in_sizes, int n_in,
                              void* d_out, int out_size) {
    const int*   atom_types = (const int*)d_in[0];
    const float* frac       = (const float*)d_in[1];
    const float* lattices   = (const float*)d_in[2];
    const float* t          = (const float*)d_in[3];
    const float* emb_table  = (const float*)d_in[7];
    const float* w_latent   = (const float*)d_in[8];
    const float* b_latent   = (const float*)d_in[9];
    const float* ew1        = (const float*)d_in[10];
    const float* eb1        = (const float*)d_in[11];
    const float* ew2        = (const float*)d_in[12];
    const float* eb2        = (const float*)d_in[13];
    const float* nw1        = (const float*)d_in[14];
    const float* nb1        = (const float*)d_in[15];
    const float* nw2        = (const float*)d_in[16];
    const float* nb2        = (const float*)d_in[17];
    const float* coord_w    = (const float*)d_in[18];
    const float* lattice_w  = (const float*)d_in[19];
    float* out = (float*)d_out;

    cudaFuncSetAttribute(k_edge_m, cudaFuncAttributeMaxDynamicSharedMemorySize, SM_TOT);
    cudaFuncSetAttribute(k_nodemlp_t, cudaFuncAttributeMaxDynamicSharedMemorySize, NM_TOT);
    cudaFuncSetAttribute(k_nodeside_t, cudaFuncAttributeMaxDynamicSharedMemorySize, NS_TOT);

    k_prep<<<(NLAYER * 106496 + 255) / 256, 256>>>(ew1, ew2, nw1, nw2);
    k_prep_emb<<<100, 128>>>(emb_table, w_latent);
    k_latip<<<G_CNT, 32>>>(lattices);
    k_embed<<<G_CNT, 128>>>(atom_types, t, w_latent, b_latent);
    k_dis<<<E_CNT / 128, 128>>>(frac);
    for (int i = 0; i < NLAYER; ++i) {
        k_nodeside_t<<<G_CNT, 256, NS_TOT>>>(i, ew1 + i * 325 * 128, eb1 + i * 128);
        k_edge_m<<<G_CNT, 512, SM_TOT>>>(i, eb2 + i * 128);
        k_nodemlp_t<<<G_CNT, 256, NM_TOT>>>(i, nb1 + i * 128, nb2 + i * 128);
    }
    k_final<<<G_CNT, 128>>>(lattices, coord_w, lattice_w, out);
}

// round 10
// speedup vs baseline: 1.5778x; 1.2428x over previous
#include <cuda_runtime.h>
#include <cuda_bf16.h>
#include <cuda_fp16.h>
#include <math.h>
#include <stdint.h>

#define G_CNT 1024
#define A_CNT 20
#define N_CNT (G_CNT * A_CNT)          // 20480
#define E_CNT (G_CNT * A_CNT * A_CNT)  // 409600
#define H_DIM 128
#define NLAYER 4

typedef unsigned long long u64;
typedef unsigned int u32;
typedef unsigned short u16;

// ---------------- scratch (device globals) ----------------
__device__ float g_h[N_CNT * H_DIM];
__device__ float g_hs[N_CNT * H_DIM];
__device__ float g_hd[N_CNT * H_DIM];
__device__ float g_agg[N_CNT * H_DIM];
__device__ float g_latip[G_CNT * 9];
__device__ float g_latterm[G_CNT * H_DIM];
__device__ float g_embT[100 * H_DIM];            // emb_table @ w_latent[:128]
__device__ u16 g_disH[(size_t)E_CNT * 64];       // dis fp16 [edge][64]
// fp16 weights, consumer-ready K-major [n][k]
__device__ u16 g_w1d[NLAYER * 128 * 64];
__device__ u16 g_w1n[NLAYER * 256 * 128];
__device__ u16 g_w2[NLAYER * 128 * 128];
__device__ u16 g_nw1[NLAYER * 128 * 256];
__device__ u16 g_nw2[NLAYER * 128 * 128];

// silu via EX2 + RCP (fast MUFU on sm_103a; tanh.approx is NOT -> R8 regression)
__device__ __forceinline__ float siluf(float x) {
    return __fdividef(x, 1.0f + __expf(-x));
}
__device__ __forceinline__ u16 h_rn(float x) {
    return __half_as_ushort(__float2half_rn(x));
}
__device__ __forceinline__ u32 pack_h2(float a, float b) {
    __half2 hh = __floats2half2_rn(a, b);
    return *(u32*)&hh;
}

__device__ __forceinline__ void mma_f16(float c[4], const u32 a[4], u32 b0, u32 b1) {
    asm volatile(
        "mma.sync.aligned.m16n8k16.row.col.f32.f16.f16.f32 "
        "{%0,%1,%2,%3}, {%4,%5,%6,%7}, {%8,%9}, {%0,%1,%2,%3};"
        : "+f"(c[0]), "+f"(c[1]), "+f"(c[2]), "+f"(c[3])
        : "r"(a[0]), "r"(a[1]), "r"(a[2]), "r"(a[3]), "r"(b0), "r"(b1));
}

// ---------------- weight prep: fp32 -> fp16 K-major, once ----------------
__global__ __launch_bounds__(256) void k_prep(
    const float* __restrict__ ew1, const float* __restrict__ ew2,
    const float* __restrict__ nw1, const float* __restrict__ nw2)
{
    int i = blockIdx.x * 256 + threadIdx.x;
    if (i >= NLAYER * 106496) return;
    int L = i / 106496, j = i % 106496;
    const float* e1 = ew1 + L * 325 * 128;
    const float* e2 = ew2 + L * 128 * 128;
    const float* n1 = nw1 + L * 256 * 128;
    const float* n2 = nw2 + L * 128 * 128;
    if (j < 8192) {                       // w1d [n=128][k=64], pad k>=60
        int n = j >> 6, k = j & 63;
        float v = (k < 60) ? e1[(265 + k) * 128 + n] : 0.f;
        g_w1d[L * 8192 + j] = h_rn(v);
    } else if (j < 40960) {               // w1n [n=256][k=128]
        int jj = j - 8192;
        int n = jj >> 7, k = jj & 127;
        float v = (n < 128) ? e1[k * 128 + n] : e1[(128 + k) * 128 + (n - 128)];
        g_w1n[L * 32768 + jj] = h_rn(v);
    } else if (j < 57344) {               // w2 [n=128][k=128]
        int jj = j - 40960;
        int n = jj >> 7, k = jj & 127;
        g_w2[L * 16384 + jj] = h_rn(e2[k * 128 + n]);
    } else if (j < 90112) {               // nw1 [n=128][k=256]
        int jj = j - 57344;
        int n = jj >> 8, k = jj & 255;
        g_nw1[L * 32768 + jj] = h_rn(n1[k * 128 + n]);
    } else {                              // nw2 [n=128][k=128]
        int jj = j - 90112;
        int n = jj >> 7, k = jj & 127;
        g_nw2[L * 16384 + jj] = h_rn(n2[k * 128 + n]);
    }
}

// ---------------- embT[a] = emb_table[a] @ w_latent[:128] ----------------
__global__ __launch_bounds__(128) void k_prep_emb(
    const float* __restrict__ emb_table, const float* __restrict__ w_latent)
{
    int a = blockIdx.x, c = threadIdx.x;
    float s = 0.f;
#pragma unroll 4
    for (int k = 0; k < 128; ++k)
        s = fmaf(emb_table[a * 128 + k], w_latent[k * 128 + c], s);
    g_embT[a * 128 + c] = s;
}

// ---------------- lat_ip = L @ L^T ----------------
__global__ void k_latip(const float* __restrict__ lattices) {
    int g = blockIdx.x, tid = threadIdx.x;
    if (tid < 9) {
        int i = tid / 3, k = tid % 3;
        float s = 0.f;
#pragma unroll
        for (int j = 0; j < 3; ++j)
            s += lattices[g * 9 + i * 3 + j] * lattices[g * 9 + k * 3 + j];
        g_latip[g * 9 + tid] = s;
    }
}

// ---------------- dis embedding -> fp16, [e][64] ----------------
__global__ __launch_bounds__(128) void k_dis(const float* __restrict__ fc) {
    __shared__ u32 hiS[128 * 33];
    int tid = threadIdx.x;
    size_t e0 = (size_t)blockIdx.x * 128;
    int e = (int)e0 + tid;
    int g = e / 400, r = e % 400;
    int src = g * 20 + r / 20;
    int dst = g * 20 + r % 20;
    u16* hrow = (u16*)(hiS + tid * 33);
#pragma unroll
    for (int c = 0; c < 3; ++c) {
        float d = fc[dst * 3 + c] - fc[src * 3 + c];
        d -= floorf(d);
        float s1, c1;
        sincospif(2.0f * d, &s1, &c1);
        float s = 0.f, co = 1.f;
        hrow[c * 10] = 0;
        hrow[30 + c * 10] = h_rn(1.f);
#pragma unroll
        for (int f = 1; f < 10; ++f) {
            float ns = s * c1 + co * s1;
            float nc = co * c1 - s * s1;
            s = ns; co = nc;
            hrow[c * 10 + f] = h_rn(s);
            hrow[30 + c * 10 + f] = h_rn(co);
        }
    }
#pragma unroll
    for (int k = 60; k < 64; ++k) hrow[k] = 0;
    __syncthreads();
    u32* gh = (u32*)g_disH + e0 * 32;
    for (int i = tid; i < 4096; i += 128)
        gh[i] = hiS[(i >> 5) * 33 + (i & 31)];
}

// ---------------- node embedding: gather(embT) + per-graph t-latent ------
// 4-way ILP on the k chain (was a serial 256-FMA dependency chain)
__global__ __launch_bounds__(128) void k_embed(
    const int* __restrict__ atom_types, const float* __restrict__ t,
    const float* __restrict__ w_latent, const float* __restrict__ b_latent)
{
    __shared__ int at[20];
    __shared__ float ts[256];
    int g = blockIdx.x, c = threadIdx.x;
    if (c < 20) at[c] = atom_types[g * 20 + c];
    ts[c] = t[g * 256 + c];
    ts[c + 128] = t[g * 256 + c + 128];
    __syncthreads();
    float t0 = b_latent[c], t1 = 0.f, t2 = 0.f, t3 = 0.f;
#pragma unroll 8
    for (int k = 0; k < 256; k += 4) {
        t0 = fmaf(ts[k],     w_latent[(128 + k) * 128 + c], t0);
        t1 = fmaf(ts[k + 1], w_latent[(129 + k) * 128 + c], t1);
        t2 = fmaf(ts[k + 2], w_latent[(130 + k) * 128 + c], t2);
        t3 = fmaf(ts[k + 3], w_latent[(131 + k) * 128 + c], t3);
    }
    float tl = (t0 + t1) + (t2 + t3);
#pragma unroll
    for (int n = 0; n < 20; ++n)
        g_h[(g * 20 + n) * H_DIM + c] = g_embT[at[n] * 128 + c] + tl;
}

// ---------------- tensor nodeside, 4 graphs/block (80 rows = 5 exact m-tiles)
#define NS4A 0                      // A 80*272 = 21760
#define NS4B 21760                  // B 256*272 = 69632
#define NS4_TOT 91392

__global__ __launch_bounds__(256, 2) void k_nodeside_t4(
    int L, const float* __restrict__ ew1, const float* __restrict__ eb1)
{
    extern __shared__ char sm[];
    int gb = blockIdx.x, tid = threadIdx.x;     // graphs 4*gb .. 4*gb+3
    int w = tid >> 5, lane = tid & 31;
    int gq = lane >> 2, tig = lane & 3;

    // lat terms for 4 graphs
    for (int i = tid; i < 512; i += 256) {
        int gg = i >> 7, c = i & 127;
        int g = gb * 4 + gg;
        float lt = eb1[c];
#pragma unroll
        for (int j = 0; j < 9; ++j)
            lt += g_latip[g * 9 + j] * ew1[(256 + j) * H_DIM + c];
        g_latterm[g * H_DIM + c] = lt;
    }
    // stage A: 80 rows x 64 u32 (fp16 pairs), stride 272 B
    for (int idx = tid; idx < 5120; idx += 256) {
        int r = idx >> 6, c2 = idx & 63;
        const float* src = g_h + ((size_t)gb * 80 + r) * 128 + c2 * 2;
        *(u32*)(sm + NS4A + r * 272 + c2 * 4) = pack_h2(src[0], src[1]);
    }
    // stage B: w1n [256][stride 272]
    {
        const u32* src = (const u32*)(g_w1n + L * 32768);
        for (int idx = tid; idx < 16384; idx += 256) {
            int n = idx >> 6, k2 = idx & 63;
            *(u32*)(sm + NS4B + n * 272 + k2 * 4) = src[idx];
        }
    }
    __syncthreads();

    int njb = w * 4;                 // each warp: 4 n-tiles x 5 m-tiles
    float acc[5][4][4];
#pragma unroll
    for (int m = 0; m < 5; ++m)
#pragma unroll
        for (int j = 0; j < 4; ++j)
            acc[m][j][0] = acc[m][j][1] = acc[m][j][2] = acc[m][j][3] = 0.f;

#pragma unroll
    for (int ks = 0; ks < 8; ++ks) {
        int kc = ks * 16 + 2 * tig;
        u32 bh[4][2];
#pragma unroll
        for (int j = 0; j < 4; ++j) {
            const char* b = sm + NS4B + ((njb + j) * 8 + gq) * 272 + kc * 2;
            bh[j][0] = *(const u32*)b;
            bh[j][1] = *(const u32*)(b + 16);
        }
#pragma unroll
        for (int m = 0; m < 5; ++m) {
            u32 ah[4];
            const char* Ab = sm + NS4A + (m * 16) * 272;
            ah[0] = *(const u32*)(Ab + gq * 272 + kc * 2);
            ah[1] = *(const u32*)(Ab + (gq + 8) * 272 + kc * 2);
            ah[2] = *(const u32*)(Ab + gq * 272 + (kc + 8) * 2);
            ah[3] = *(const u32*)(Ab + (gq + 8) * 272 + (kc + 8) * 2);
#pragma unroll
            for (int j = 0; j < 4; ++j)
                mma_f16(acc[m][j], ah, bh[j][0], bh[j][1]);
        }
    }
    // store: rows all real (80 exact)
#pragma unroll
    for (int m = 0; m < 5; ++m) {
        int rowA = m * 16 + gq, rowB = rowA + 8;
#pragma unroll
        for (int j = 0; j < 4; ++j) {
            int n = (njb + j) * 8 + 2 * tig;
            size_t baseA = ((size_t)gb * 80 + rowA) * 128;
            size_t baseB = ((size_t)gb * 80 + rowB) * 128;
            float* dA = (n < 128) ? (g_hs + baseA + n) : (g_hd + baseA + n - 128);
            float* dB = (n < 128) ? (g_hs + baseB + n) : (g_hd + baseB + n - 128);
            *(float2*)dA = make_float2(acc[m][j][0], acc[m][j][1]);
            *(float2*)dB = make_float2(acc[m][j][2], acc[m][j][3]);
        }
    }
}

// ---------------- tensor (mma.sync fp16) edge kernel (unchanged, proven) ----
#define SW1 0           // W1d [128][72 halves] 18432
#define SW2 18432       // W2 [128][136] 34816
#define SAW 53248       // 16 warps x 4352
#define SHS 122880
#define SHD 133120
#define SLAT 143360
#define SB2 143872
#define SPART 144384    // [25][2][128] f32 = 25600
#define SM_TOT 169984

__global__ __launch_bounds__(512, 1) void k_edge_m(
    int L, const float* __restrict__ eb2)
{
    extern __shared__ char sm[];
    int tid = threadIdx.x, g0 = blockIdx.x;
    int w = tid >> 5, lane = tid & 31;
    int gq = lane >> 2, tig = lane & 3;

    {
        const u32* src = (const u32*)(g_w1d + L * 8192);
        for (int idx = tid; idx < 4096; idx += 512) {
            int n = idx >> 5, k2 = idx & 31;
            *(u32*)(sm + SW1 + n * 144 + k2 * 4) = src[idx];
        }
    }
    {
        const u32* src = (const u32*)(g_w2 + L * 16384);
        for (int idx = tid; idx < 8192; idx += 512) {
            int n = idx >> 6, k2 = idx & 63;
            *(u32*)(sm + SW2 + n * 272 + k2 * 4) = src[idx];
        }
    }
    float* hs = (float*)(sm + SHS);
    float* hd = (float*)(sm + SHD);
    for (int i = tid; i < 2560; i += 512) {
        hs[i] = g_hs[g0 * 2560 + i];
        hd[i] = g_hd[g0 * 2560 + i];
    }
    if (tid < 128) {
        ((float*)(sm + SLAT))[tid] = g_latterm[g0 * H_DIM + tid];
        ((float*)(sm + SB2))[tid] = eb2[tid];
    }
    __syncthreads();

    char* AB = sm + SAW + w * 4352;
    float* lat = (float*)(sm + SLAT);
    float* b2 = (float*)(sm + SB2);
    float* part = (float*)(sm + SPART);

    for (int tt = w; tt < 25; tt += 16) {
        int e0 = tt * 16;
        {
            const uint4* sH = (const uint4*)(g_disH + ((size_t)g0 * 400 + e0) * 64);
#pragma unroll
            for (int q = 0; q < 4; ++q) {
                int idx = lane + q * 32;
                int row = idx >> 3, seg = idx & 7;
                *(uint4*)(AB + row * 144 + seg * 16) = sH[row * 8 + seg];
            }
        }
        __syncwarp();

        float acc[16][4];
#pragma unroll
        for (int j = 0; j < 16; ++j)
            acc[j][0] = acc[j][1] = acc[j][2] = acc[j][3] = 0.f;
#pragma unroll
        for (int ks = 0; ks < 4; ++ks) {
            int kc = ks * 16 + 2 * tig;
            u32 ah[4];
            ah[0] = *(const u32*)(AB + gq * 144 + kc * 2);
            ah[1] = *(const u32*)(AB + (gq + 8) * 144 + kc * 2);
            ah[2] = *(const u32*)(AB + gq * 144 + (kc + 8) * 2);
            ah[3] = *(const u32*)(AB + (gq + 8) * 144 + (kc + 8) * 2);
#pragma unroll
            for (int j = 0; j < 16; ++j) {
                const char* bh = sm + SW1 + ((j * 8 + gq) * 72 + kc) * 2;
                mma_f16(acc[j], ah, *(const u32*)bh, *(const u32*)(bh + 16));
            }
        }
        __syncwarp();

        {
            int eA = e0 + gq, eB = e0 + gq + 8;
            int srcA = eA / 20, dstA = eA - srcA * 20;
            int srcB = eB / 20, dstB = eB - srcB * 20;
#pragma unroll
            for (int j = 0; j < 16; ++j) {
                int c0 = j * 8 + 2 * tig;
                float2 la = *(const float2*)&lat[c0];
                float2 hsA = *(const float2*)&hs[srcA * 128 + c0];
                float2 hdA = *(const float2*)&hd[dstA * 128 + c0];
                float2 hsB = *(const float2*)&hs[srcB * 128 + c0];
                float2 hdB = *(const float2*)&hd[dstB * 128 + c0];
                float x0 = siluf(acc[j][0] + hsA.x + hdA.x + la.x);
                float x1 = siluf(acc[j][1] + hsA.y + hdA.y + la.y);
                float x2 = siluf(acc[j][2] + hsB.x + hdB.x + la.x);
                float x3 = siluf(acc[j][3] + hsB.y + hdB.y + la.y);
                *(u32*)(AB + gq * 272 + c0 * 2) = pack_h2(x0, x1);
                *(u32*)(AB + (gq + 8) * 272 + c0 * 2) = pack_h2(x2, x3);
            }
        }
        __syncwarp();

        float acc2[16][4];
#pragma unroll
        for (int j = 0; j < 16; ++j)
            acc2[j][0] = acc2[j][1] = acc2[j][2] = acc2[j][3] = 0.f;
#pragma unroll
        for (int ks = 0; ks < 8; ++ks) {
            int kc = ks * 16 + 2 * tig;
            u32 ah[4];
            ah[0] = *(const u32*)(AB + gq * 272 + kc * 2);
            ah[1] = *(const u32*)(AB + (gq + 8) * 272 + kc * 2);
            ah[2] = *(const u32*)(AB + gq * 272 + (kc + 8) * 2);
            ah[3] = *(const u32*)(AB + (gq + 8) * 272 + (kc + 8) * 2);
#pragma unroll
            for (int j = 0; j < 16; ++j) {
                const char* bh = sm + SW2 + ((j * 8 + gq) * 136 + kc) * 2;
                mma_f16(acc2[j], ah, *(const u32*)bh, *(const u32*)(bh + 16));
            }
        }

        {
            float* ef = (float*)AB;
            int sA = e0 / 20;
            int bnd = 20 * (sA + 1) - e0;
            if (bnd > 16) bnd = 16;
#pragma unroll
            for (int half = 0; half < 2; ++half) {
                __syncwarp();
#pragma unroll
                for (int j = half * 8; j < half * 8 + 8; ++j) {
                    int c0 = j * 8 + 2 * tig;
                    float2 bb = *(const float2*)&b2[c0];
                    float2 v0, v1;
                    v0.x = siluf(acc2[j][0] + bb.x);
                    v0.y = siluf(acc2[j][1] + bb.y);
                    v1.x = siluf(acc2[j][2] + bb.x);
                    v1.y = siluf(acc2[j][3] + bb.y);
                    int cl = c0 - half * 64;
                    *(float2*)&ef[gq * 68 + cl] = v0;
                    *(float2*)&ef[(gq + 8) * 68 + cl] = v1;
                }
                __syncwarp();
                int cl = 2 * lane;
                float2 p0 = make_float2(0.f, 0.f), p1 = make_float2(0.f, 0.f);
#pragma unroll
                for (int r = 0; r < 16; ++r) {
                    float2 v = *(const float2*)&ef[r * 68 + cl];
                    if (r < bnd) { p0.x += v.x; p0.y += v.y; }
                    else { p1.x += v.x; p1.y += v.y; }
                }
                *(float2*)&part[(tt * 2) * 128 + half * 64 + cl] = p0;
                *(float2*)&part[(tt * 2 + 1) * 128 + half * 64 + cl] = p1;
            }
        }
        __syncwarp();
    }
    __syncthreads();

    for (int idx = tid; idx < 2560; idx += 512) {
        int s = idx >> 7, c = idx & 127;
        int t0 = (20 * s) >> 4, t1 = (20 * s + 19) >> 4;
        float a = 0.f;
        for (int t = t0; t <= t1; ++t) {
            int sA = (16 * t) / 20;
            int sB = (16 * t + 15) / 20;
            if (sA == s) a += part[t * 256 + c];
            else if (sB == s) a += part[t * 256 + 128 + c];
        }
        g_agg[g0 * 2560 + idx] = a * 0.05f;
    }
}

// ---------------- tensor node MLP + residual, 4 graphs/block ----------------
#define NMA1 0          // 80*528 = 42240
#define NMB1 42240      // 128*528 = 67584 -> 109824
#define NMA2 109824     // 80*272 = 21760 -> 131584
#define NMB2 131584     // 128*272 = 34816 -> 166400
#define NM_TOT 166400

__global__ __launch_bounds__(256, 1) void k_nodemlp_t4(
    int L, const float* __restrict__ nb1, const float* __restrict__ nb2)
{
    extern __shared__ char sm[];
    int gb = blockIdx.x, tid = threadIdx.x;
    int w = tid >> 5, lane = tid & 31;
    int gq = lane >> 2, tig = lane & 3;

    // stage A1: 80 rows x [h | agg] -> fp16, stride 528 B
    for (int idx = tid; idx < 10240; idx += 256) {
        int r = idx >> 7, c2 = idx & 127;
        float a0, a1;
        size_t base = ((size_t)gb * 80 + r) * 128;
        if (c2 < 64) {
            const float* s = g_h + base + c2 * 2;
            a0 = s[0]; a1 = s[1];
        } else {
            const float* s = g_agg + base + (c2 - 64) * 2;
            a0 = s[0]; a1 = s[1];
        }
        *(u32*)(sm + NMA1 + r * 528 + c2 * 4) = pack_h2(a0, a1);
    }
    {
        const u32* src = (const u32*)(g_nw1 + L * 32768);
        for (int idx = tid; idx < 16384; idx += 256) {
            int n = idx >> 7, k2 = idx & 127;
            *(u32*)(sm + NMB1 + n * 528 + k2 * 4) = src[idx];
        }
        const u32* src2 = (const u32*)(g_nw2 + L * 16384);
        for (int idx = tid; idx < 8192; idx += 256) {
            int n = idx >> 6, k2 = idx & 63;
            *(u32*)(sm + NMB2 + n * 272 + k2 * 4) = src2[idx];
        }
    }
    __syncthreads();

    int njb = w * 2;                 // each warp: 2 n-tiles x 5 m-tiles
    // ---- GEMM1: [80,256] @ [256,128] ----
    float acc[5][2][4];
#pragma unroll
    for (int m = 0; m < 5; ++m)
#pragma unroll
        for (int j = 0; j < 2; ++j)
            acc[m][j][0] = acc[m][j][1] = acc[m][j][2] = acc[m][j][3] = 0.f;
#pragma unroll
    for (int ks = 0; ks < 16; ++ks) {
        int kc = ks * 16 + 2 * tig;
        u32 bh[2][2];
#pragma unroll
        for (int j = 0; j < 2; ++j) {
            const char* b = sm + NMB1 + ((njb + j) * 8 + gq) * 528 + kc * 2;
            bh[j][0] = *(const u32*)b;
            bh[j][1] = *(const u32*)(b + 16);
        }
#pragma unroll
        for (int m = 0; m < 5; ++m) {
            u32 ah[4];
            const char* Ab = sm + NMA1 + (m * 16) * 528;
            ah[0] = *(const u32*)(Ab + gq * 528 + kc * 2);
            ah[1] = *(const u32*)(Ab + (gq + 8) * 528 + kc * 2);
            ah[2] = *(const u32*)(Ab + gq * 528 + (kc + 8) * 2);
            ah[3] = *(const u32*)(Ab + (gq + 8) * 528 + (kc + 8) * 2);
#pragma unroll
            for (int j = 0; j < 2; ++j)
                mma_f16(acc[m][j], ah, bh[j][0], bh[j][1]);
        }
    }
    // epilogue 1: silu -> A2 fp16
#pragma unroll
    for (int m = 0; m < 5; ++m) {
        int rA = m * 16 + gq;
#pragma unroll
        for (int j = 0; j < 2; ++j) {
            int c0 = (njb + j) * 8 + 2 * tig;
            float bb0 = __ldg(nb1 + c0), bb1 = __ldg(nb1 + c0 + 1);
            *(u32*)(sm + NMA2 + rA * 272 + c0 * 2) =
                pack_h2(siluf(acc[m][j][0] + bb0), siluf(acc[m][j][1] + bb1));
            *(u32*)(sm + NMA2 + (rA + 8) * 272 + c0 * 2) =
                pack_h2(siluf(acc[m][j][2] + bb0), siluf(acc[m][j][3] + bb1));
        }
    }
    __syncthreads();

    // ---- GEMM2: [80,128] @ [128,128] ----
    float acc2[5][2][4];
#pragma unroll
    for (int m = 0; m < 5; ++m)
#pragma unroll
        for (int j = 0; j < 2; ++j)
            acc2[m][j][0] = acc2[m][j][1] = acc2[m][j][2] = acc2[m][j][3] = 0.f;
#pragma unroll
    for (int ks = 0; ks < 8; ++ks) {
        int kc = ks * 16 + 2 * tig;
        u32 bh[2][2];
#pragma unroll
        for (int j = 0; j < 2; ++j) {
            const char* b = sm + NMB2 + ((njb + j) * 8 + gq) * 272 + kc * 2;
            bh[j][0] = *(const u32*)b;
            bh[j][1] = *(const u32*)(b + 16);
        }
#pragma unroll
        for (int m = 0; m < 5; ++m) {
            u32 ah[4];
            const char* Ab = sm + NMA2 + (m * 16) * 272;
            ah[0] = *(const u32*)(Ab + gq * 272 + kc * 2);
            ah[1] = *(const u32*)(Ab + (gq + 8) * 272 + kc * 2);
            ah[2] = *(const u32*)(Ab + gq * 272 + (kc + 8) * 2);
            ah[3] = *(const u32*)(Ab + (gq + 8) * 272 + (kc + 8) * 2);
#pragma unroll
            for (int j = 0; j < 2; ++j)
                mma_f16(acc2[m][j], ah, bh[j][0], bh[j][1]);
        }
    }
    // epilogue 2: h += silu(acc2 + nb2); all 80 rows real
#pragma unroll
    for (int m = 0; m < 5; ++m) {
        int rA = m * 16 + gq, rB = rA + 8;
#pragma unroll
        for (int j = 0; j < 2; ++j) {
            int c0 = (njb + j) * 8 + 2 * tig;
            float bb0 = __ldg(nb2 + c0), bb1 = __ldg(nb2 + c0 + 1);
            {
                float* d = g_h + ((size_t)gb * 80 + rA) * 128 + c0;
                float2 o = *(float2*)d;
                o.x += siluf(acc2[m][j][0] + bb0);
                o.y += siluf(acc2[m][j][1] + bb1);
                *(float2*)d = o;
            }
            {
                float* d = g_h + ((size_t)gb * 80 + rB) * 128 + c0;
                float2 o = *(float2*)d;
                o.x += siluf(acc2[m][j][2] + bb0);
                o.y += siluf(acc2[m][j][3] + bb1);
                *(float2*)d = o;
            }
        }
    }
}

// ---------------- output heads ----------------
__global__ __launch_bounds__(128) void k_final(
    const float* __restrict__ lattices, const float* __restrict__ coord_w,
    const float* __restrict__ lattice_w, float* __restrict__ out)
{
    __shared__ __align__(16) float hT[128 * 20];
    __shared__ float gf[128];
    __shared__ float pre[9];
    int g = blockIdx.x, tid = threadIdx.x;
    for (int n = 0; n < 20; ++n)
        hT[tid * 20 + n] = g_h[(g * 20 + n) * H_DIM + tid];
    __syncthreads();
    float s = 0.f;
#pragma unroll
    for (int n = 0; n < 20; ++n) s += hT[tid * 20 + n];
    gf[tid] = s * 0.05f;
    __syncthreads();
    if (tid < 9) {
        float acc = 0.f;
        for (int k = 0; k < 128; ++k) acc += gf[k] * lattice_w[k * 9 + tid];
        pre[tid] = acc;
    }
    __syncthreads();
    if (tid < 9) {
        int i = tid / 3, kk = tid % 3;
        float v = 0.f;
#pragma unroll
        for (int j = 0; j < 3; ++j)
            v += pre[i * 3 + j] * lattices[g * 9 + j * 3 + kk];
        out[g * 9 + tid] = v;
    }
    if (tid < 60) {
        int n = tid / 3, c = tid % 3;
        float acc = 0.f;
        for (int k = 0; k < 128; ++k) acc += hT[k * 20 + n] * coord_w[k * 3 + c];
        out[G_CNT * 9 + (g * 20 + n) * 3 + c] = acc;
    }
}

// ---------------- launch ----------------
extern "C" void kernel_launch(void* const* d_in, const int* in_sizes, int n_in,
                              void* d_out, int out_size) {
    const int*   atom_types = (const int*)d_in[0];
    const float* frac       = (const float*)d_in[1];
    const float* lattices   = (const float*)d_in[2];
    const float* t          = (const float*)d_in[3];
    const float* emb_table  = (const float*)d_in[7];
    const float* w_latent   = (const float*)d_in[8];
    const float* b_latent   = (const float*)d_in[9];
    const float* ew1        = (const float*)d_in[10];
    const float* eb1        = (const float*)d_in[11];
    const float* ew2        = (const float*)d_in[12];
    const float* eb2        = (const float*)d_in[13];
    const float* nw1        = (const float*)d_in[14];
    const float* nb1        = (const float*)d_in[15];
    const float* nw2        = (const float*)d_in[16];
    const float* nb2        = (const float*)d_in[17];
    const float* coord_w    = (const float*)d_in[18];
    const float* lattice_w  = (const float*)d_in[19];
    float* out = (float*)d_out;

    cudaFuncSetAttribute(k_edge_m, cudaFuncAttributeMaxDynamicSharedMemorySize, SM_TOT);
    cudaFuncSetAttribute(k_nodemlp_t4, cudaFuncAttributeMaxDynamicSharedMemorySize, NM_TOT);
    cudaFuncSetAttribute(k_nodeside_t4, cudaFuncAttributeMaxDynamicSharedMemorySize, NS4_TOT);

    k_prep<<<(NLAYER * 106496 + 255) / 256, 256>>>(ew1, ew2, nw1, nw2);
    k_prep_emb<<<100, 128>>>(emb_table, w_latent);
    k_latip<<<G_CNT, 32>>>(lattices);
    k_embed<<<G_CNT, 128>>>(atom_types, t, w_latent, b_latent);
    k_dis<<<E_CNT / 128, 128>>>(frac);
    for (int i = 0; i < NLAYER; ++i) {
        k_nodeside_t4<<<G_CNT / 4, 256, NS4_TOT>>>(i, ew1 + i * 325 * 128, eb1 + i * 128);
        k_edge_m<<<G_CNT, 512, SM_TOT>>>(i, eb2 + i * 128);
        k_nodemlp_t4<<<G_CNT / 4, 256, NM_TOT>>>(i, nb1 + i * 128, nb2 + i * 128);
    }
    k_final<<<G_CNT, 128>>>(lattices, coord_w, lattice_w, out);
}

// round 11
// speedup vs baseline: 1.8313x; 1.1607x over previous
#include <cuda_runtime.h>
#include <cuda_bf16.h>
#include <cuda_fp16.h>
#include <math.h>
#include <stdint.h>

#define G_CNT 1024
#define A_CNT 20
#define N_CNT (G_CNT * A_CNT)          // 20480
#define E_CNT (G_CNT * A_CNT * A_CNT)  // 409600
#define H_DIM 128
#define NLAYER 4
#define EDGE_GRID 148

typedef unsigned long long u64;
typedef unsigned int u32;
typedef unsigned short u16;

// ---------------- scratch (device globals) ----------------
__device__ float g_h[N_CNT * H_DIM];
__device__ float g_hs[N_CNT * H_DIM];
__device__ float g_hd[N_CNT * H_DIM];
__device__ float g_agg[N_CNT * H_DIM];
__device__ float g_latip[G_CNT * 9];
__device__ float g_latterm[G_CNT * H_DIM];
__device__ float g_embT[100 * H_DIM];            // emb_table @ w_latent[:128]
__device__ u16 g_disH[(size_t)E_CNT * 64];       // dis fp16 [edge][64]
// fp16 weights, consumer-ready K-major [n][k]
__device__ u16 g_w1d[NLAYER * 128 * 64];
__device__ u16 g_w1n[NLAYER * 256 * 128];
__device__ u16 g_w2[NLAYER * 128 * 128];
__device__ u16 g_nw1[NLAYER * 128 * 256];
__device__ u16 g_nw2[NLAYER * 128 * 128];

// silu via EX2 + RCP (fast MUFU on sm_103a; tanh.approx is NOT -> R8 regression)
__device__ __forceinline__ float siluf(float x) {
    return __fdividef(x, 1.0f + __expf(-x));
}
__device__ __forceinline__ u16 h_rn(float x) {
    return __half_as_ushort(__float2half_rn(x));
}
__device__ __forceinline__ u32 pack_h2(float a, float b) {
    __half2 hh = __floats2half2_rn(a, b);
    return *(u32*)&hh;
}

__device__ __forceinline__ void mma_f16(float c[4], const u32 a[4], u32 b0, u32 b1) {
    asm volatile(
        "mma.sync.aligned.m16n8k16.row.col.f32.f16.f16.f32 "
        "{%0,%1,%2,%3}, {%4,%5,%6,%7}, {%8,%9}, {%0,%1,%2,%3};"
        : "+f"(c[0]), "+f"(c[1]), "+f"(c[2]), "+f"(c[3])
        : "r"(a[0]), "r"(a[1]), "r"(a[2]), "r"(a[3]), "r"(b0), "r"(b1));
}

// ---------------- weight prep: fp32 -> fp16 K-major, once ----------------
__global__ __launch_bounds__(256) void k_prep(
    const float* __restrict__ ew1, const float* __restrict__ ew2,
    const float* __restrict__ nw1, const float* __restrict__ nw2)
{
    int i = blockIdx.x * 256 + threadIdx.x;
    if (i >= NLAYER * 106496) return;
    int L = i / 106496, j = i % 106496;
    const float* e1 = ew1 + L * 325 * 128;
    const float* e2 = ew2 + L * 128 * 128;
    const float* n1 = nw1 + L * 256 * 128;
    const float* n2 = nw2 + L * 128 * 128;
    if (j < 8192) {                       // w1d [n=128][k=64], pad k>=60
        int n = j >> 6, k = j & 63;
        float v = (k < 60) ? e1[(265 + k) * 128 + n] : 0.f;
        g_w1d[L * 8192 + j] = h_rn(v);
    } else if (j < 40960) {               // w1n [n=256][k=128]
        int jj = j - 8192;
        int n = jj >> 7, k = jj & 127;
        float v = (n < 128) ? e1[k * 128 + n] : e1[(128 + k) * 128 + (n - 128)];
        g_w1n[L * 32768 + jj] = h_rn(v);
    } else if (j < 57344) {               // w2 [n=128][k=128]
        int jj = j - 40960;
        int n = jj >> 7, k = jj & 127;
        g_w2[L * 16384 + jj] = h_rn(e2[k * 128 + n]);
    } else if (j < 90112) {               // nw1 [n=128][k=256]
        int jj = j - 57344;
        int n = jj >> 8, k = jj & 255;
        g_nw1[L * 32768 + jj] = h_rn(n1[k * 128 + n]);
    } else {                              // nw2 [n=128][k=128]
        int jj = j - 90112;
        int n = jj >> 7, k = jj & 127;
        g_nw2[L * 16384 + jj] = h_rn(n2[k * 128 + n]);
    }
}

// ---------------- embT[a] = emb_table[a] @ w_latent[:128] ----------------
__global__ __launch_bounds__(128) void k_prep_emb(
    const float* __restrict__ emb_table, const float* __restrict__ w_latent)
{
    int a = blockIdx.x, c = threadIdx.x;
    float s = 0.f;
#pragma unroll 4
    for (int k = 0; k < 128; ++k)
        s = fmaf(emb_table[a * 128 + k], w_latent[k * 128 + c], s);
    g_embT[a * 128 + c] = s;
}

// ---------------- lat_ip = L @ L^T ----------------
__global__ void k_latip(const float* __restrict__ lattices) {
    int g = blockIdx.x, tid = threadIdx.x;
    if (tid < 9) {
        int i = tid / 3, k = tid % 3;
        float s = 0.f;
#pragma unroll
        for (int j = 0; j < 3; ++j)
            s += lattices[g * 9 + i * 3 + j] * lattices[g * 9 + k * 3 + j];
        g_latip[g * 9 + tid] = s;
    }
}

// ---------------- dis embedding -> fp16, [e][64] ----------------
__global__ __launch_bounds__(128) void k_dis(const float* __restrict__ fc) {
    __shared__ u32 hiS[128 * 33];
    int tid = threadIdx.x;
    size_t e0 = (size_t)blockIdx.x * 128;
    int e = (int)e0 + tid;
    int g = e / 400, r = e % 400;
    int src = g * 20 + r / 20;
    int dst = g * 20 + r % 20;
    u16* hrow = (u16*)(hiS + tid * 33);
#pragma unroll
    for (int c = 0; c < 3; ++c) {
        float d = fc[dst * 3 + c] - fc[src * 3 + c];
        d -= floorf(d);
        float s1, c1;
        sincospif(2.0f * d, &s1, &c1);
        float s = 0.f, co = 1.f;
        hrow[c * 10] = 0;
        hrow[30 + c * 10] = h_rn(1.f);
#pragma unroll
        for (int f = 1; f < 10; ++f) {
            float ns = s * c1 + co * s1;
            float nc = co * c1 - s * s1;
            s = ns; co = nc;
            hrow[c * 10 + f] = h_rn(s);
            hrow[30 + c * 10 + f] = h_rn(co);
        }
    }
#pragma unroll
    for (int k = 60; k < 64; ++k) hrow[k] = 0;
    __syncthreads();
    u32* gh = (u32*)g_disH + e0 * 32;
    for (int i = tid; i < 4096; i += 128)
        gh[i] = hiS[(i >> 5) * 33 + (i & 31)];
}

// ---------------- node embedding ----------------
__global__ __launch_bounds__(128) void k_embed(
    const int* __restrict__ atom_types, const float* __restrict__ t,
    const float* __restrict__ w_latent, const float* __restrict__ b_latent)
{
    __shared__ int at[20];
    __shared__ float ts[256];
    int g = blockIdx.x, c = threadIdx.x;
    if (c < 20) at[c] = atom_types[g * 20 + c];
    ts[c] = t[g * 256 + c];
    ts[c + 128] = t[g * 256 + c + 128];
    __syncthreads();
    float t0 = b_latent[c], t1 = 0.f, t2 = 0.f, t3 = 0.f;
#pragma unroll 8
    for (int k = 0; k < 256; k += 4) {
        t0 = fmaf(ts[k],     w_latent[(128 + k) * 128 + c], t0);
        t1 = fmaf(ts[k + 1], w_latent[(129 + k) * 128 + c], t1);
        t2 = fmaf(ts[k + 2], w_latent[(130 + k) * 128 + c], t2);
        t3 = fmaf(ts[k + 3], w_latent[(131 + k) * 128 + c], t3);
    }
    float tl = (t0 + t1) + (t2 + t3);
#pragma unroll
    for (int n = 0; n < 20; ++n)
        g_h[(g * 20 + n) * H_DIM + c] = g_embT[at[n] * 128 + c] + tl;
}

// ---------------- tensor nodeside, 4 graphs/block ----------------
#define NS4A 0                      // A 80*272 = 21760
#define NS4B 21760                  // B 256*272 = 69632
#define NS4_TOT 91392

__global__ __launch_bounds__(256, 2) void k_nodeside_t4(
    int L, const float* __restrict__ ew1, const float* __restrict__ eb1)
{
    extern __shared__ char sm[];
    int gb = blockIdx.x, tid = threadIdx.x;
    int w = tid >> 5, lane = tid & 31;
    int gq = lane >> 2, tig = lane & 3;

    for (int i = tid; i < 512; i += 256) {
        int gg = i >> 7, c = i & 127;
        int g = gb * 4 + gg;
        float lt = eb1[c];
#pragma unroll
        for (int j = 0; j < 9; ++j)
            lt += g_latip[g * 9 + j] * ew1[(256 + j) * H_DIM + c];
        g_latterm[g * H_DIM + c] = lt;
    }
    for (int idx = tid; idx < 5120; idx += 256) {
        int r = idx >> 6, c2 = idx & 63;
        const float* src = g_h + ((size_t)gb * 80 + r) * 128 + c2 * 2;
        *(u32*)(sm + NS4A + r * 272 + c2 * 4) = pack_h2(src[0], src[1]);
    }
    {
        const u32* src = (const u32*)(g_w1n + L * 32768);
        for (int idx = tid; idx < 16384; idx += 256) {
            int n = idx >> 6, k2 = idx & 63;
            *(u32*)(sm + NS4B + n * 272 + k2 * 4) = src[idx];
        }
    }
    __syncthreads();

    int njb = w * 4;
    float acc[5][4][4];
#pragma unroll
    for (int m = 0; m < 5; ++m)
#pragma unroll
        for (int j = 0; j < 4; ++j)
            acc[m][j][0] = acc[m][j][1] = acc[m][j][2] = acc[m][j][3] = 0.f;

#pragma unroll
    for (int ks = 0; ks < 8; ++ks) {
        int kc = ks * 16 + 2 * tig;
        u32 bh[4][2];
#pragma unroll
        for (int j = 0; j < 4; ++j) {
            const char* b = sm + NS4B + ((njb + j) * 8 + gq) * 272 + kc * 2;
            bh[j][0] = *(const u32*)b;
            bh[j][1] = *(const u32*)(b + 16);
        }
#pragma unroll
        for (int m = 0; m < 5; ++m) {
            u32 ah[4];
            const char* Ab = sm + NS4A + (m * 16) * 272;
            ah[0] = *(const u32*)(Ab + gq * 272 + kc * 2);
            ah[1] = *(const u32*)(Ab + (gq + 8) * 272 + kc * 2);
            ah[2] = *(const u32*)(Ab + gq * 272 + (kc + 8) * 2);
            ah[3] = *(const u32*)(Ab + (gq + 8) * 272 + (kc + 8) * 2);
#pragma unroll
            for (int j = 0; j < 4; ++j)
                mma_f16(acc[m][j], ah, bh[j][0], bh[j][1]);
        }
    }
#pragma unroll
    for (int m = 0; m < 5; ++m) {
        int rowA = m * 16 + gq, rowB = rowA + 8;
#pragma unroll
        for (int j = 0; j < 4; ++j) {
            int n = (njb + j) * 8 + 2 * tig;
            size_t baseA = ((size_t)gb * 80 + rowA) * 128;
            size_t baseB = ((size_t)gb * 80 + rowB) * 128;
            float* dA = (n < 128) ? (g_hs + baseA + n) : (g_hd + baseA + n - 128);
            float* dB = (n < 128) ? (g_hs + baseB + n) : (g_hd + baseB + n - 128);
            *(float2*)dA = make_float2(acc[m][j][0], acc[m][j][1]);
            *(float2*)dB = make_float2(acc[m][j][2], acc[m][j][3]);
        }
    }
}

// ---------------- persistent tensor edge kernel ----------------
// grid = 148 blocks x 512 thr; each block loops graphs b, b+148, ...
// Weights + b2 staged ONCE. lat folded into hs at per-graph staging.
#define SW1 0           // W1d [128][72 halves] 18432
#define SW2 18432       // W2 [128][136] 34816
#define SAW 53248       // 16 warps x 4352
#define SHS 122880
#define SHD 133120
#define SLAT 143360     // (unused; kept for layout)
#define SB2 143872
#define SPART 144384    // [25][2][128] f32 = 25600
#define SM_TOT 169984

__global__ __launch_bounds__(512, 1) void k_edge_p(
    int L, const float* __restrict__ eb2)
{
    extern __shared__ char sm[];
    int tid = threadIdx.x;
    int w = tid >> 5, lane = tid & 31;
    int gq = lane >> 2, tig = lane & 3;

    // ---- stage weights + b2 once ----
    {
        const u32* src = (const u32*)(g_w1d + L * 8192);
        for (int idx = tid; idx < 4096; idx += 512) {
            int n = idx >> 5, k2 = idx & 31;
            *(u32*)(sm + SW1 + n * 144 + k2 * 4) = src[idx];
        }
        const u32* src2 = (const u32*)(g_w2 + L * 16384);
        for (int idx = tid; idx < 8192; idx += 512) {
            int n = idx >> 6, k2 = idx & 63;
            *(u32*)(sm + SW2 + n * 272 + k2 * 4) = src2[idx];
        }
        if (tid < 128) ((float*)(sm + SB2))[tid] = eb2[tid];
    }

    float* hs = (float*)(sm + SHS);
    float* hd = (float*)(sm + SHD);
    float* b2 = (float*)(sm + SB2);
    float* part = (float*)(sm + SPART);
    char* AB = sm + SAW + w * 4352;

    for (int g0 = blockIdx.x; g0 < G_CNT; g0 += EDGE_GRID) {
        __syncthreads();   // prior graph fully consumed (part read, hs/hd reads done)
        // ---- per-graph staging: hs (+latterm folded), hd ----
        for (int i = tid; i < 2560; i += 512) {
            hs[i] = g_hs[g0 * 2560 + i] + g_latterm[g0 * H_DIM + (i & 127)];
            hd[i] = g_hd[g0 * 2560 + i];
        }
        __syncthreads();

        for (int tt = w; tt < 25; tt += 16) {
            int e0 = tt * 16;
            {
                const uint4* sH = (const uint4*)(g_disH + ((size_t)g0 * 400 + e0) * 64);
#pragma unroll
                for (int q = 0; q < 4; ++q) {
                    int idx = lane + q * 32;
                    int row = idx >> 3, seg = idx & 7;
                    *(uint4*)(AB + row * 144 + seg * 16) = sH[row * 8 + seg];
                }
            }
            __syncwarp();

            // ---- GEMM1: dis[16,64] @ W1d[64,128] ----
            float acc[16][4];
#pragma unroll
            for (int j = 0; j < 16; ++j)
                acc[j][0] = acc[j][1] = acc[j][2] = acc[j][3] = 0.f;
#pragma unroll
            for (int ks = 0; ks < 4; ++ks) {
                int kc = ks * 16 + 2 * tig;
                u32 ah[4];
                ah[0] = *(const u32*)(AB + gq * 144 + kc * 2);
                ah[1] = *(const u32*)(AB + (gq + 8) * 144 + kc * 2);
                ah[2] = *(const u32*)(AB + gq * 144 + (kc + 8) * 2);
                ah[3] = *(const u32*)(AB + (gq + 8) * 144 + (kc + 8) * 2);
#pragma unroll
                for (int j = 0; j < 16; ++j) {
                    const char* bh = sm + SW1 + ((j * 8 + gq) * 72 + kc) * 2;
                    mma_f16(acc[j], ah, *(const u32*)bh, *(const u32*)(bh + 16));
                }
            }
            __syncwarp();

            // ---- epilogue A: + hs[src](lat folded) + hd[dst], silu -> A2 ----
            {
                int eA = e0 + gq, eB = e0 + gq + 8;
                int srcA = eA / 20, dstA = eA - srcA * 20;
                int srcB = eB / 20, dstB = eB - srcB * 20;
#pragma unroll
                for (int j = 0; j < 16; ++j) {
                    int c0 = j * 8 + 2 * tig;
                    float2 hsA = *(const float2*)&hs[srcA * 128 + c0];
                    float2 hdA = *(const float2*)&hd[dstA * 128 + c0];
                    float2 hsB = *(const float2*)&hs[srcB * 128 + c0];
                    float2 hdB = *(const float2*)&hd[dstB * 128 + c0];
                    float x0 = siluf(acc[j][0] + hsA.x + hdA.x);
                    float x1 = siluf(acc[j][1] + hsA.y + hdA.y);
                    float x2 = siluf(acc[j][2] + hsB.x + hdB.x);
                    float x3 = siluf(acc[j][3] + hsB.y + hdB.y);
                    *(u32*)(AB + gq * 272 + c0 * 2) = pack_h2(x0, x1);
                    *(u32*)(AB + (gq + 8) * 272 + c0 * 2) = pack_h2(x2, x3);
                }
            }
            __syncwarp();

            // ---- GEMM2: ef[16,128] @ W2[128,128] ----
            float acc2[16][4];
#pragma unroll
            for (int j = 0; j < 16; ++j)
                acc2[j][0] = acc2[j][1] = acc2[j][2] = acc2[j][3] = 0.f;
#pragma unroll
            for (int ks = 0; ks < 8; ++ks) {
                int kc = ks * 16 + 2 * tig;
                u32 ah[4];
                ah[0] = *(const u32*)(AB + gq * 272 + kc * 2);
                ah[1] = *(const u32*)(AB + (gq + 8) * 272 + kc * 2);
                ah[2] = *(const u32*)(AB + gq * 272 + (kc + 8) * 2);
                ah[3] = *(const u32*)(AB + (gq + 8) * 272 + (kc + 8) * 2);
#pragma unroll
                for (int j = 0; j < 16; ++j) {
                    const char* bh = sm + SW2 + ((j * 8 + gq) * 136 + kc) * 2;
                    mma_f16(acc2[j], ah, *(const u32*)bh, *(const u32*)(bh + 16));
                }
            }

            // ---- epilogue B ----
            {
                float* ef = (float*)AB;
                int sA = e0 / 20;
                int bnd = 20 * (sA + 1) - e0;
                if (bnd > 16) bnd = 16;
#pragma unroll
                for (int half = 0; half < 2; ++half) {
                    __syncwarp();
#pragma unroll
                    for (int j = half * 8; j < half * 8 + 8; ++j) {
                        int c0 = j * 8 + 2 * tig;
                        float2 bb = *(const float2*)&b2[c0];
                        float2 v0, v1;
                        v0.x = siluf(acc2[j][0] + bb.x);
                        v0.y = siluf(acc2[j][1] + bb.y);
                        v1.x = siluf(acc2[j][2] + bb.x);
                        v1.y = siluf(acc2[j][3] + bb.y);
                        int cl = c0 - half * 64;
                        *(float2*)&ef[gq * 68 + cl] = v0;
                        *(float2*)&ef[(gq + 8) * 68 + cl] = v1;
                    }
                    __syncwarp();
                    int cl = 2 * lane;
                    float2 p0 = make_float2(0.f, 0.f), p1 = make_float2(0.f, 0.f);
#pragma unroll
                    for (int r = 0; r < 16; ++r) {
                        float2 v = *(const float2*)&ef[r * 68 + cl];
                        if (r < bnd) { p0.x += v.x; p0.y += v.y; }
                        else { p1.x += v.x; p1.y += v.y; }
                    }
                    *(float2*)&part[(tt * 2) * 128 + half * 64 + cl] = p0;
                    *(float2*)&part[(tt * 2 + 1) * 128 + half * 64 + cl] = p1;
                }
            }
            __syncwarp();
        }
        __syncthreads();

        // ---- combine partials -> scatter-mean ----
        for (int idx = tid; idx < 2560; idx += 512) {
            int s = idx >> 7, c = idx & 127;
            int t0 = (20 * s) >> 4, t1 = (20 * s + 19) >> 4;
            float a = 0.f;
            for (int t = t0; t <= t1; ++t) {
                int sA = (16 * t) / 20;
                int sB = (16 * t + 15) / 20;
                if (sA == s) a += part[t * 256 + c];
                else if (sB == s) a += part[t * 256 + 128 + c];
            }
            g_agg[g0 * 2560 + idx] = a * 0.05f;
        }
    }
}

// ---------------- tensor node MLP + residual, 8 graphs/block ----------------
// A1 [160][528B]; after GEMM1 sync, A1 region is reused for A2 [160][272B]
// and B2 [128][272B] (aliasing is safe: all A1 reads complete at the sync).
#define M8A1 0          // 160*528 = 84480
#define M8B1 84480      // 128*528 = 67584 -> 152064
#define M8A2 0          // 160*272 = 43520 (aliases A1)
#define M8B2 43520      // 128*272 = 34816 (aliases A1) -> ends 78336
#define M8_TOT 152064

__global__ __launch_bounds__(256, 1) void k_nodemlp_t8(
    int L, const float* __restrict__ nb1, const float* __restrict__ nb2)
{
    extern __shared__ char sm[];
    int gb = blockIdx.x, tid = threadIdx.x;    // graphs 8*gb .. 8*gb+7
    int w = tid >> 5, lane = tid & 31;
    int gq = lane >> 2, tig = lane & 3;

    // stage A1: 160 rows x [h | agg] -> fp16, stride 528 B
    for (int idx = tid; idx < 20480; idx += 256) {
        int r = idx >> 7, c2 = idx & 127;
        float a0, a1;
        size_t base = ((size_t)gb * 160 + r) * 128;
        if (c2 < 64) {
            const float* s = g_h + base + c2 * 2;
            a0 = s[0]; a1 = s[1];
        } else {
            const float* s = g_agg + base + (c2 - 64) * 2;
            a0 = s[0]; a1 = s[1];
        }
        *(u32*)(sm + M8A1 + r * 528 + c2 * 4) = pack_h2(a0, a1);
    }
    {
        const u32* src = (const u32*)(g_nw1 + L * 32768);
        for (int idx = tid; idx < 16384; idx += 256) {
            int n = idx >> 7, k2 = idx & 127;
            *(u32*)(sm + M8B1 + n * 528 + k2 * 4) = src[idx];
        }
    }
    __syncthreads();

    int njb = w * 2;                 // each warp: 2 n-tiles x 10 m-tiles
    // ---- GEMM1: [160,256] @ [256,128] ----
    float acc[10][2][4];
#pragma unroll
    for (int m = 0; m < 10; ++m)
#pragma unroll
        for (int j = 0; j < 2; ++j)
            acc[m][j][0] = acc[m][j][1] = acc[m][j][2] = acc[m][j][3] = 0.f;
#pragma unroll
    for (int ks = 0; ks < 16; ++ks) {
        int kc = ks * 16 + 2 * tig;
        u32 bh[2][2];
#pragma unroll
        for (int j = 0; j < 2; ++j) {
            const char* b = sm + M8B1 + ((njb + j) * 8 + gq) * 528 + kc * 2;
            bh[j][0] = *(const u32*)b;
            bh[j][1] = *(const u32*)(b + 16);
        }
#pragma unroll
        for (int m = 0; m < 10; ++m) {
            u32 ah[4];
            const char* Ab = sm + M8A1 + (m * 16) * 528;
            ah[0] = *(const u32*)(Ab + gq * 528 + kc * 2);
            ah[1] = *(const u32*)(Ab + (gq + 8) * 528 + kc * 2);
            ah[2] = *(const u32*)(Ab + gq * 528 + (kc + 8) * 2);
            ah[3] = *(const u32*)(Ab + (gq + 8) * 528 + (kc + 8) * 2);
#pragma unroll
            for (int j = 0; j < 2; ++j)
                mma_f16(acc[m][j], ah, bh[j][0], bh[j][1]);
        }
    }
    __syncthreads();   // all A1 reads done -> safe to overwrite with A2/B2

    // epilogue 1: silu -> A2 fp16 (into old A1 space) + stage B2
#pragma unroll
    for (int m = 0; m < 10; ++m) {
        int rA = m * 16 + gq;
#pragma unroll
        for (int j = 0; j < 2; ++j) {
            int c0 = (njb + j) * 8 + 2 * tig;
            float bb0 = __ldg(nb1 + c0), bb1 = __ldg(nb1 + c0 + 1);
            *(u32*)(sm + M8A2 + rA * 272 + c0 * 2) =
                pack_h2(siluf(acc[m][j][0] + bb0), siluf(acc[m][j][1] + bb1));
            *(u32*)(sm + M8A2 + (rA + 8) * 272 + c0 * 2) =
                pack_h2(siluf(acc[m][j][2] + bb0), siluf(acc[m][j][3] + bb1));
        }
    }
    {
        const u32* src2 = (const u32*)(g_nw2 + L * 16384);
        for (int idx = tid; idx < 8192; idx += 256) {
            int n = idx >> 6, k2 = idx & 63;
            *(u32*)(sm + M8B2 + n * 272 + k2 * 4) = src2[idx];
        }
    }
    __syncthreads();

    // ---- GEMM2: [160,128] @ [128,128] ----
    float acc2[10][2][4];
#pragma unroll
    for (int m = 0; m < 10; ++m)
#pragma unroll
        for (int j = 0; j < 2; ++j)
            acc2[m][j][0] = acc2[m][j][1] = acc2[m][j][2] = acc2[m][j][3] = 0.f;
#pragma unroll
    for (int ks = 0; ks < 8; ++ks) {
        int kc = ks * 16 + 2 * tig;
        u32 bh[2][2];
#pragma unroll
        for (int j = 0; j < 2; ++j) {
            const char* b = sm + M8B2 + ((njb + j) * 8 + gq) * 272 + kc * 2;
            bh[j][0] = *(const u32*)b;
            bh[j][1] = *(const u32*)(b + 16);
        }
#pragma unroll
        for (int m = 0; m < 10; ++m) {
            u32 ah[4];
            const char* Ab = sm + M8A2 + (m * 16) * 272;
            ah[0] = *(const u32*)(Ab + gq * 272 + kc * 2);
            ah[1] = *(const u32*)(Ab + (gq + 8) * 272 + kc * 2);
            ah[2] = *(const u32*)(Ab + gq * 272 + (kc + 8) * 2);
            ah[3] = *(const u32*)(Ab + (gq + 8) * 272 + (kc + 8) * 2);
#pragma unroll
            for (int j = 0; j < 2; ++j)
                mma_f16(acc2[m][j], ah, bh[j][0], bh[j][1]);
        }
    }
    // epilogue 2: h += silu(acc2 + nb2); all 160 rows real
#pragma unroll
    for (int m = 0; m < 10; ++m) {
        int rA = m * 16 + gq, rB = rA + 8;
#pragma unroll
        for (int j = 0; j < 2; ++j) {
            int c0 = (njb + j) * 8 + 2 * tig;
            float bb0 = __ldg(nb2 + c0), bb1 = __ldg(nb2 + c0 + 1);
            {
                float* d = g_h + ((size_t)gb * 160 + rA) * 128 + c0;
                float2 o = *(float2*)d;
                o.x += siluf(acc2[m][j][0] + bb0);
                o.y += siluf(acc2[m][j][1] + bb1);
                *(float2*)d = o;
            }
            {
                float* d = g_h + ((size_t)gb * 160 + rB) * 128 + c0;
                float2 o = *(float2*)d;
                o.x += siluf(acc2[m][j][2] + bb0);
                o.y += siluf(acc2[m][j][3] + bb1);
                *(float2*)d = o;
            }
        }
    }
}

// ---------------- output heads ----------------
__global__ __launch_bounds__(128) void k_final(
    const float* __restrict__ lattices, const float* __restrict__ coord_w,
    const float* __restrict__ lattice_w, float* __restrict__ out)
{
    __shared__ __align__(16) float hT[128 * 20];
    __shared__ float gf[128];
    __shared__ float pre[9];
    int g = blockIdx.x, tid = threadIdx.x;
    for (int n = 0; n < 20; ++n)
        hT[tid * 20 + n] = g_h[(g * 20 + n) * H_DIM + tid];
    __syncthreads();
    float s = 0.f;
#pragma unroll
    for (int n = 0; n < 20; ++n) s += hT[tid * 20 + n];
    gf[tid] = s * 0.05f;
    __syncthreads();
    if (tid < 9) {
        float acc = 0.f;
        for (int k = 0; k < 128; ++k) acc += gf[k] * lattice_w[k * 9 + tid];
        pre[tid] = acc;
    }
    __syncthreads();
    if (tid < 9) {
        int i = tid / 3, kk = tid % 3;
        float v = 0.f;
#pragma unroll
        for (int j = 0; j < 3; ++j)
            v += pre[i * 3 + j] * lattices[g * 9 + j * 3 + kk];
        out[g * 9 + tid] = v;
    }
    if (tid < 60) {
        int n = tid / 3, c = tid % 3;
        float acc = 0.f;
        for (int k = 0; k < 128; ++k) acc += hT[k * 20 + n] * coord_w[k * 3 + c];
        out[G_CNT * 9 + (g * 20 + n) * 3 + c] = acc;
    }
}

// ---------------- launch ----------------
extern "C" void kernel_launch(void* const* d_in, const int* in_sizes, int n_in,
                              void* d_out, int out_size) {
    const int*   atom_types = (const int*)d_in[0];
    const float* frac       = (const float*)d_in[1];
    const float* lattices   = (const float*)d_in[2];
    const float* t          = (const float*)d_in[3];
    const float* emb_table  = (const float*)d_in[7];
    const float* w_latent   = (const float*)d_in[8];
    const float* b_latent   = (const float*)d_in[9];
    const float* ew1        = (const float*)d_in[10];
    const float* eb1        = (const float*)d_in[11];
    const float* ew2        = (const float*)d_in[12];
    const float* eb2        = (const float*)d_in[13];
    const float* nw1        = (const float*)d_in[14];
    const float* nb1        = (const float*)d_in[15];
    const float* nw2        = (const float*)d_in[16];
    const float* nb2        = (const float*)d_in[17];
    const float* coord_w    = (const float*)d_in[18];
    const float* lattice_w  = (const float*)d_in[19];
    float* out = (float*)d_out;

    cudaFuncSetAttribute(k_edge_p, cudaFuncAttributeMaxDynamicSharedMemorySize, SM_TOT);
    cudaFuncSetAttribute(k_nodemlp_t8, cudaFuncAttributeMaxDynamicSharedMemorySize, M8_TOT);
    cudaFuncSetAttribute(k_nodeside_t4, cudaFuncAttributeMaxDynamicSharedMemorySize, NS4_TOT);

    k_prep<<<(NLAYER * 106496 + 255) / 256, 256>>>(ew1, ew2, nw1, nw2);
    k_prep_emb<<<100, 128>>>(emb_table, w_latent);
    k_latip<<<G_CNT, 32>>>(lattices);
    k_embed<<<G_CNT, 128>>>(atom_types, t, w_latent, b_latent);
    k_dis<<<E_CNT / 128, 128>>>(frac);
    for (int i = 0; i < NLAYER; ++i) {
        k_nodeside_t4<<<G_CNT / 4, 256, NS4_TOT>>>(i, ew1 + i * 325 * 128, eb1 + i * 128);
        k_edge_p<<<EDGE_GRID, 512, SM_TOT>>>(i, eb2 + i * 128);
        k_nodemlp_t8<<<G_CNT / 8, 256, M8_TOT>>>(i, nb1 + i * 128, nb2 + i * 128);
    }
    k_final<<<G_CNT, 128>>>(lattices, coord_w, lattice_w, out);
}